// round 9
// baseline (speedup 1.0000x reference)
#include <cuda_runtime.h>
#include <cuda_bf16.h>
#include <math.h>
#include <cstdint>

// Problem dims
#define TT   512
#define BB   64
#define EE   300
#define HH   512
#define LL   5
#define TH3  1536   // 3*H

#define KP0  320    // padded K for layer-0 input GEMM (E=300 -> 320)
#define KP1  512    // K for layer-1 input GEMM

// ---------------- scratch (device globals; no allocation allowed) -------------
__device__ float g_xp [(size_t)TT * TH3 * BB];   // input projections [T][3H][B]
__device__ float g_ys0[(size_t)TT * HH  * BB];   // layer0 hidden seq [T][H][B]
__device__ float g_ys1[(size_t)TT * HH  * BB];   // layer1 hidden seq [T][H][B]

// split-bf16 (hi+lo) operands for tensor-core GEMMs
__device__ __nv_bfloat16 g_embh[(size_t)30000 * KP0];
__device__ __nv_bfloat16 g_embl[(size_t)30000 * KP0];
__device__ __nv_bfloat16 g_w0h [(size_t)TH3 * KP0];
__device__ __nv_bfloat16 g_w0l [(size_t)TH3 * KP0];
__device__ __nv_bfloat16 g_w1h [(size_t)TH3 * KP1];
__device__ __nv_bfloat16 g_w1l [(size_t)TH3 * KP1];
__device__ __nv_bfloat16 g_a1h [(size_t)TT * BB * KP1];   // ys0 transposed [m=t*64+b][k]
__device__ __nv_bfloat16 g_a1l [(size_t)TT * BB * KP1];

// Whh split-bf16 for tensor-core recurrence
__device__ __nv_bfloat16 g_whh0h[(size_t)TH3 * HH];
__device__ __nv_bfloat16 g_whh0l[(size_t)TH3 * HH];
__device__ __nv_bfloat16 g_whh1h[(size_t)TH3 * HH];
__device__ __nv_bfloat16 g_whh1l[(size_t)TH3 * HH];

// h(t) broadcast buffers: [buf 2][b 64][kpair 256][hi0,hi1,lo0,lo1]
// -> bf16 index ((buf*64 + b)*256 + (k>>1))*4 + (hi? (k&1) : 2+(k&1))
__device__ __nv_bfloat16 g_hb[(size_t)2 * BB * (HH / 2) * 4];

__device__ unsigned g_bar_count = 0;
__device__ unsigned g_bar_sense = 0;

// ======================= helpers (base ISA only; no sm_103a-only ops) =========
__device__ __forceinline__ uint32_t smem_u32(const void* p) {
    uint32_t a;
    asm("{ .reg .u64 t; cvta.to.shared.u64 t, %1; cvt.u32.u64 %0, t; }" : "=r"(a) : "l"(p));
    return a;
}
__device__ __forceinline__ void cp16(uint32_t dst, const void* src) {
    asm volatile("cp.async.cg.shared.global [%0], [%1], 16;" :: "r"(dst), "l"(src));
}
__device__ __forceinline__ void cp_commit() { asm volatile("cp.async.commit_group;" ::: "memory"); }
__device__ __forceinline__ void cp_wait1()  { asm volatile("cp.async.wait_group 1;" ::: "memory"); }
__device__ __forceinline__ void cp_wait0()  { asm volatile("cp.async.wait_group 0;" ::: "memory"); }

__device__ __forceinline__ void mma_bf16(float* c, uint32_t a0, uint32_t a1,
                                         uint32_t a2, uint32_t a3,
                                         uint32_t b0, uint32_t b1) {
    asm volatile(
        "mma.sync.aligned.m16n8k16.row.col.f32.bf16.bf16.f32 "
        "{%0,%1,%2,%3}, {%4,%5,%6,%7}, {%8,%9}, {%0,%1,%2,%3};"
        : "+f"(c[0]), "+f"(c[1]), "+f"(c[2]), "+f"(c[3])
        : "r"(a0), "r"(a1), "r"(a2), "r"(a3), "r"(b0), "r"(b1));
}

// Sense-reversing grid barrier. All CTAs co-resident (128 on 148 SMs). State
// returns to {0,0} after an even number of uses per launch (512 per launch).
__device__ __forceinline__ void grid_barrier(unsigned* lsense, int nb) {
    __syncthreads();
    if (threadIdx.x == 0) {
        unsigned s = *lsense ^ 1u;
        __threadfence();
        if (atomicAdd(&g_bar_count, 1u) == (unsigned)(nb - 1)) {
            g_bar_count = 0u;
            __threadfence();
            atomicExch(&g_bar_sense, s);
        } else {
            volatile unsigned* vs = &g_bar_sense;
            while (*vs != s) { __nanosleep(32); }
        }
        __threadfence();
    }
    __syncthreads();
    *lsense ^= 1u;
}

// =================== conversion kernels (fp32 -> bf16 hi/lo) ==================
__global__ __launch_bounds__(256) void k_conv_pair(
    const float* __restrict__ src, __nv_bfloat16* __restrict__ dh,
    __nv_bfloat16* __restrict__ dl, int N, int Ks, int Kp)
{
    size_t total = (size_t)N * Kp;
    for (size_t idx = (size_t)blockIdx.x * blockDim.x + threadIdx.x; idx < total;
         idx += (size_t)gridDim.x * blockDim.x) {
        int n = (int)(idx / Kp), k = (int)(idx - (size_t)n * Kp);
        float v = (k < Ks) ? src[(size_t)n * Ks + k] : 0.f;
        __nv_bfloat16 hi = __float2bfloat16(v);
        dh[idx] = hi;
        dl[idx] = __float2bfloat16(v - __bfloat162float(hi));
    }
}

// transpose-convert g_ys0 [T][H][B] -> g_a1h/l [m=t*64+b][k=H]
__global__ __launch_bounds__(256) void k_conv_ys0() {
    __shared__ float smt[64][65];
    int t = blockIdx.x, kb = blockIdx.y;     // grid (512, 8)
    const float* src = g_ys0 + ((size_t)t * HH + kb * 64) * BB;
    for (int i = threadIdx.x; i < 4096; i += 256) {
        int k = i >> 6, b = i & 63;
        smt[k][b] = src[(size_t)k * BB + b];
    }
    __syncthreads();
    for (int i = threadIdx.x; i < 4096; i += 256) {
        int b = i >> 6, k = i & 63;
        float v = smt[k][b];
        __nv_bfloat16 hi = __float2bfloat16(v);
        size_t o = ((size_t)t * 64 + b) * KP1 + kb * 64 + k;
        g_a1h[o] = hi;
        g_a1l[o] = __float2bfloat16(v - __bfloat162float(hi));
    }
}

// ============== HMMA split-bf16 GEMM (input projections) ======================
// C[m][n] = sum_k (Ah+Al)[row(m)][k]*(Bh+Bl)[n][k] + bias[n]  (drops Al*Bl).
// CTA 256 thr, tile 128x128, K stage 32, cp.async double buffer.
#define STRD32 20                       // row stride in b32 units
#define TILE_BYTES (128 * 80)           // 10240
#define STAGE_BYTES (4 * TILE_BYTES)    // Ah, Al, Bh, Bl
#define GEMM_SMEM (2 * STAGE_BYTES)     // 81920

__global__ __launch_bounds__(256) void k_mma_gemm(
    const __nv_bfloat16* __restrict__ Ah, const __nv_bfloat16* __restrict__ Al,
    const int* __restrict__ rowidx,     // null => identity (row = m)
    int Kpad, int S,
    const __nv_bfloat16* __restrict__ Bh, const __nv_bfloat16* __restrict__ Bl,
    const float* __restrict__ bias)
{
    extern __shared__ __align__(128) char smem[];
    __shared__ int   rows_s[128];
    __shared__ float bias_s[128];

    const int tid = threadIdx.x;
    const int bn = blockIdx.x, bm = blockIdx.y;
    const uint32_t sb = smem_u32(smem);

    if (tid < 128) {
        int m = bm * 128 + tid;
        rows_s[tid] = rowidx ? rowidx[m] : m;
        bias_s[tid] = bias[bn * 128 + tid];
    }
    __syncthreads();

    auto load_stage = [&](int s) {
        uint32_t buf = sb + (uint32_t)(s & 1) * STAGE_BYTES;
        int k0 = s * 32;
#pragma unroll
        for (int i = 0; i < 8; i++) {
            int idx = tid + i * 256;          // 2048 cp16 total
            int tile = idx >> 9;
            int loc = idx & 511;
            int r = loc >> 2, c = loc & 3;
            const __nv_bfloat16* src;
            if (tile < 2) {
                src = (tile == 0 ? Ah : Al) + (size_t)rows_s[r] * Kpad + k0 + c * 8;
            } else {
                src = (tile == 2 ? Bh : Bl) + (size_t)(bn * 128 + r) * Kpad + k0 + c * 8;
            }
            cp16(buf + tile * TILE_BYTES + r * 80 + c * 16, src);
        }
        cp_commit();
    };

    load_stage(0);
    if (S > 1) load_stage(1);

    const int wid = tid >> 5, lane = tid & 31;
    const int wm = wid & 3, wn = wid >> 2;
    const int g = lane >> 2, q = lane & 3;

    float acc[2][8][4];
#pragma unroll
    for (int mt = 0; mt < 2; mt++)
#pragma unroll
        for (int nt = 0; nt < 8; nt++)
#pragma unroll
            for (int e = 0; e < 4; e++) acc[mt][nt][e] = 0.f;

    for (int s = 0; s < S; s++) {
        if (s + 1 < S) cp_wait1(); else cp_wait0();
        __syncthreads();
        const char* buf = smem + (size_t)(s & 1) * STAGE_BYTES;
        const uint32_t* Ah32 = (const uint32_t*)(buf);
        const uint32_t* Al32 = (const uint32_t*)(buf + TILE_BYTES);
        const uint32_t* Bh32 = (const uint32_t*)(buf + 2 * TILE_BYTES);
        const uint32_t* Bl32 = (const uint32_t*)(buf + 3 * TILE_BYTES);

#pragma unroll
        for (int kh = 0; kh < 2; kh++) {
            const int kb = kh * 8;
            uint32_t ah[2][4], al[2][4];
#pragma unroll
            for (int mt = 0; mt < 2; mt++) {
                int r0 = (wm * 32 + mt * 16 + g) * STRD32;
                int r1 = r0 + 8 * STRD32;
                ah[mt][0] = Ah32[r0 + kb + q];
                ah[mt][1] = Ah32[r1 + kb + q];
                ah[mt][2] = Ah32[r0 + kb + q + 4];
                ah[mt][3] = Ah32[r1 + kb + q + 4];
                al[mt][0] = Al32[r0 + kb + q];
                al[mt][1] = Al32[r1 + kb + q];
                al[mt][2] = Al32[r0 + kb + q + 4];
                al[mt][3] = Al32[r1 + kb + q + 4];
            }
#pragma unroll
            for (int nt = 0; nt < 8; nt++) {
                int nr = (wn * 64 + nt * 8 + g) * STRD32;
                uint32_t bh0 = Bh32[nr + kb + q];
                uint32_t bh1 = Bh32[nr + kb + q + 4];
                uint32_t bl0 = Bl32[nr + kb + q];
                uint32_t bl1 = Bl32[nr + kb + q + 4];
#pragma unroll
                for (int mt = 0; mt < 2; mt++) {
                    mma_bf16(acc[mt][nt], ah[mt][0], ah[mt][1], ah[mt][2], ah[mt][3], bh0, bh1);
                    mma_bf16(acc[mt][nt], ah[mt][0], ah[mt][1], ah[mt][2], ah[mt][3], bl0, bl1);
                    mma_bf16(acc[mt][nt], al[mt][0], al[mt][1], al[mt][2], al[mt][3], bh0, bh1);
                }
            }
        }
        __syncthreads();
        if (s + 2 < S) load_stage(s + 2);
    }

#pragma unroll
    for (int mt = 0; mt < 2; mt++) {
        int r0 = wm * 32 + mt * 16 + g;
        int m0 = bm * 128 + r0;
        int m1 = m0 + 8;
        float* p0 = g_xp + ((size_t)(m0 >> 6) * TH3) * BB + (m0 & 63);
        float* p1 = g_xp + ((size_t)(m1 >> 6) * TH3) * BB + (m1 & 63);
#pragma unroll
        for (int nt = 0; nt < 8; nt++) {
            int c = wn * 64 + nt * 8 + q * 2;
            int n0 = bn * 128 + c;
            float bv0 = bias_s[c], bv1 = bias_s[c + 1];
            p0[(size_t)n0 * BB]       = acc[mt][nt][0] + bv0;
            p0[(size_t)(n0 + 1) * BB] = acc[mt][nt][1] + bv1;
            p1[(size_t)n0 * BB]       = acc[mt][nt][2] + bv0;
            p1[(size_t)(n0 + 1) * BB] = acc[mt][nt][3] + bv1;
        }
    }
}

// ============== tensor-core persistent GRU recurrence (one layer) =============
// Grid 128 CTAs x 512 thr. CTA owns 4 hidden cols j -> 12 gate rows (pad m=16).
// gh[m=16][b=64] = W[16][512] @ h[b][512]^T via mma.sync m16n8k16 split-bf16.
// Warp w: n-tile nt=w&7 (8 b), k-half kh=w>>3 (k in [kh*256, kh*256+256)).
// h(t-1) broadcast: global bf16, [b][kpair][hi0,hi1,lo0,lo1], double-buffered.
__device__ __forceinline__ float fsigm(float x) {
    return __fdividef(1.f, 1.f + __expf(-x));
}
__device__ __forceinline__ float ftanh(float x) {
    return 1.f - __fdividef(2.f, 1.f + __expf(2.f * x));
}

__global__ __launch_bounds__(512, 1) void k_recur_mma(
    const __nv_bfloat16* __restrict__ Wh,   // [3H][512] bf16 hi
    const __nv_bfloat16* __restrict__ Wl,   // [3H][512] bf16 lo
    const float* __restrict__ bhh,          // [3H]
    int layer)
{
    __shared__ __align__(16) __nv_bfloat16 Ah_s[16][520];
    __shared__ __align__(16) __nv_bfloat16 Al_s[16][520];
    __shared__ __align__(16) float red[2][16][64];    // [kh][m][b]
    __shared__ float bhh_s[12];

    float* __restrict__ ys = layer ? g_ys1 : g_ys0;
    const float* __restrict__ xp = g_xp;

    const int tid   = threadIdx.x;
    const int jbase = blockIdx.x * 4;
    const int nbk   = gridDim.x;

    // Load W gate rows (m = g*4 + jl -> global row g*H + jbase + jl); pad 12..15
    for (int idx = tid; idx < 16 * 512; idx += 512) {
        int m = idx >> 9, k = idx & 511;
        __nv_bfloat16 vh = __float2bfloat16(0.f);
        __nv_bfloat16 vl = vh;
        if (m < 12) {
            int gg = m >> 2, jl = m & 3;
            size_t off = ((size_t)(gg * HH + jbase + jl)) * HH + k;
            vh = Wh[off]; vl = Wl[off];
        }
        Ah_s[m][k] = vh; Al_s[m][k] = vl;
    }
    if (tid < 12) {
        int gg = tid >> 2, jl = tid & 3;
        bhh_s[tid] = bhh[gg * HH + jbase + jl];
    }
    __syncthreads();

    const int warp = tid >> 5;
    const int lane = tid & 31;
    const int nt = warp & 7;
    const int kh = warp >> 3;
    const int g = lane >> 2;         // fragment group id
    const int q = lane & 3;
    const int q2 = q * 2;
    const int nidx = nt * 8 + g;     // batch index this lane's B fragment covers
    const int nb = nt * 8 + q2;      // C fragment column base

    // tail-thread persistent state (tid < 256)
    const int rjl = tid >> 6, rb = tid & 63;
    float hq = 0.f;

    unsigned lsense = 0;

    for (int t = 0; t < TT; t++) {
        // tail prefetch of xp for this step
        float xr = 0.f, xz = 0.f, xn = 0.f;
        if (tid < 256) {
            const float* xpb = xp + (size_t)t * TH3 * BB + rb;
            int j = jbase + rjl;
            xr = __ldcg(xpb + (size_t)(0 * HH + j) * BB);
            xz = __ldcg(xpb + (size_t)(1 * HH + j) * BB);
            xn = __ldcg(xpb + (size_t)(2 * HH + j) * BB);
        }

        if (t > 0) {
            const int rbuf = (t - 1) & 1;
            const __nv_bfloat16* Bb = g_hb + (size_t)rbuf * (BB * 1024)
                                           + (size_t)nidx * 1024;
            float acc[4] = {0.f, 0.f, 0.f, 0.f};
#pragma unroll
            for (int s = 0; s < 16; s++) {
                const int k0 = kh * 256 + s * 16;
                const int w0 = (k0 >> 1) + q;    // k-pair index
                float2 v0 = __ldcg((const float2*)(Bb + (size_t)w0 * 4));
                float2 v1 = __ldcg((const float2*)(Bb + (size_t)(w0 + 4) * 4));
                uint32_t bh0 = __float_as_uint(v0.x);
                uint32_t bl0 = __float_as_uint(v0.y);
                uint32_t bh1 = __float_as_uint(v1.x);
                uint32_t bl1 = __float_as_uint(v1.y);
                uint32_t ah0 = *(const uint32_t*)&Ah_s[g][k0 + q2];
                uint32_t ah1 = *(const uint32_t*)&Ah_s[g + 8][k0 + q2];
                uint32_t ah2 = *(const uint32_t*)&Ah_s[g][k0 + q2 + 8];
                uint32_t ah3 = *(const uint32_t*)&Ah_s[g + 8][k0 + q2 + 8];
                uint32_t al0 = *(const uint32_t*)&Al_s[g][k0 + q2];
                uint32_t al1 = *(const uint32_t*)&Al_s[g + 8][k0 + q2];
                uint32_t al2 = *(const uint32_t*)&Al_s[g][k0 + q2 + 8];
                uint32_t al3 = *(const uint32_t*)&Al_s[g + 8][k0 + q2 + 8];
                mma_bf16(acc, ah0, ah1, ah2, ah3, bh0, bh1);
                mma_bf16(acc, ah0, ah1, ah2, ah3, bl0, bl1);
                mma_bf16(acc, al0, al1, al2, al3, bh0, bh1);
            }
            red[kh][g][nb]         = acc[0];
            red[kh][g][nb + 1]     = acc[1];
            red[kh][g + 8][nb]     = acc[2];
            red[kh][g + 8][nb + 1] = acc[3];
        }
        __syncthreads();

        if (tid < 256) {
            float s0 = bhh_s[0 + rjl];
            float s1 = bhh_s[4 + rjl];
            float s2 = bhh_s[8 + rjl];
            if (t > 0) {
                s0 += red[0][rjl][rb]     + red[1][rjl][rb];
                s1 += red[0][4 + rjl][rb] + red[1][4 + rjl][rb];
                s2 += red[0][8 + rjl][rb] + red[1][8 + rjl][rb];
            }
            float r = fsigm(xr + s0);
            float z = fsigm(xz + s1);
            float n = ftanh(xn + r * s2);
            float hnew = (1.f - z) * n + z * hq;
            hq = hnew;

            int j = jbase + rjl;
            ys[((size_t)t * HH + j) * BB + rb] = hnew;

            // write bf16 hi/lo broadcast for next step
            __nv_bfloat16 hi = __float2bfloat16(hnew);
            __nv_bfloat16 lo = __float2bfloat16(hnew - __bfloat162float(hi));
            int p = j >> 1, pos = j & 1;
            size_t hb = (size_t)(t & 1) * (BB * 1024) + (size_t)rb * 1024
                        + (size_t)p * 4;
            g_hb[hb + pos]     = hi;
            g_hb[hb + 2 + pos] = lo;
        }
        grid_barrier(&lsense, nbk);
    }
}

// ==================== mean over batch + FC head ===============================
__global__ __launch_bounds__(256) void k_pool(
    const float* __restrict__ fcW,
    const float* __restrict__ fcb,
    float*       __restrict__ out)
{
    int t = blockIdx.x;
    const float* base = g_ys1 + (size_t)t * HH * BB;
    int w = threadIdx.x >> 5, l = threadIdx.x & 31;

    float acc[LL];
#pragma unroll
    for (int j = 0; j < LL; j++) acc[j] = 0.f;

    for (int h = w; h < HH; h += 8) {
        float s = base[h * BB + l] + base[h * BB + 32 + l];
#pragma unroll
        for (int off = 16; off >= 1; off >>= 1)
            s += __shfl_xor_sync(0xffffffffu, s, off);
        if (l == 0) {
            float p = s * (1.f / 64.f);
#pragma unroll
            for (int j = 0; j < LL; j++) acc[j] = fmaf(p, fcW[j * HH + h], acc[j]);
        }
    }
    __shared__ float sred[8][LL];
    if (l == 0) {
#pragma unroll
        for (int j = 0; j < LL; j++) sred[w][j] = acc[j];
    }
    __syncthreads();
    if (threadIdx.x < LL) {
        float s = fcb[threadIdx.x];
#pragma unroll
        for (int ww = 0; ww < 8; ww++) s += sred[ww][threadIdx.x];
        out[t * LL + threadIdx.x] = s;
    }
}

// ============================== launch ========================================
extern "C" void kernel_launch(void* const* d_in, const int* in_sizes, int n_in,
                              void* d_out, int out_size) {
    const int*   texts = (const int*)  d_in[0];
    const float* emb   = (const float*)d_in[1];
    const float* Wih0  = (const float*)d_in[2];
    const float* Whh0  = (const float*)d_in[3];
    const float* bih0  = (const float*)d_in[4];
    const float* bhh0  = (const float*)d_in[5];
    const float* Wih1  = (const float*)d_in[6];
    const float* Whh1  = (const float*)d_in[7];
    const float* bih1  = (const float*)d_in[8];
    const float* bhh1  = (const float*)d_in[9];
    const float* fcW   = (const float*)d_in[10];
    const float* fcb   = (const float*)d_in[11];
    float* out = (float*)d_out;

    cudaFuncSetAttribute(k_mma_gemm, cudaFuncAttributeMaxDynamicSharedMemorySize,
                         GEMM_SMEM);

    // resolve device-global scratch addresses for kernel params
    __nv_bfloat16 *embh, *embl, *w0h, *w0l, *w1h, *w1l, *a1h, *a1l;
    __nv_bfloat16 *wh0h, *wh0l, *wh1h, *wh1l;
    cudaGetSymbolAddress((void**)&embh, g_embh);
    cudaGetSymbolAddress((void**)&embl, g_embl);
    cudaGetSymbolAddress((void**)&w0h,  g_w0h);
    cudaGetSymbolAddress((void**)&w0l,  g_w0l);
    cudaGetSymbolAddress((void**)&w1h,  g_w1h);
    cudaGetSymbolAddress((void**)&w1l,  g_w1l);
    cudaGetSymbolAddress((void**)&a1h,  g_a1h);
    cudaGetSymbolAddress((void**)&a1l,  g_a1l);
    cudaGetSymbolAddress((void**)&wh0h, g_whh0h);
    cudaGetSymbolAddress((void**)&wh0l, g_whh0l);
    cudaGetSymbolAddress((void**)&wh1h, g_whh1h);
    cudaGetSymbolAddress((void**)&wh1l, g_whh1l);

    dim3 gemm_grid(TH3 / 128, (TT * BB) / 128);   // (12, 256)

    // conversions (static operands)
    k_conv_pair<<<8192, 256>>>(emb,  embh, embl, 30000, EE, KP0);
    k_conv_pair<<<1024, 256>>>(Wih0, w0h,  w0l,  TH3,   EE, KP0);
    k_conv_pair<<<1024, 256>>>(Wih1, w1h,  w1l,  TH3,   HH, KP1);
    k_conv_pair<<<768,  256>>>(Whh0, wh0h, wh0l, TH3,   HH, HH);
    k_conv_pair<<<768,  256>>>(Whh1, wh1h, wh1l, TH3,   HH, HH);

    // Layer 0: xp = emb[texts] @ Wih0^T + bih0 (HMMA), then tensor recurrence
    k_mma_gemm<<<gemm_grid, 256, GEMM_SMEM>>>(embh, embl, texts, KP0, KP0 / 32,
                                              w0h, w0l, bih0);
    k_recur_mma<<<128, 512>>>(wh0h, wh0l, bhh0, 0);

    // Layer 1: transpose-convert ys0, xp = ys0 @ Wih1^T + bih1, recurrence
    k_conv_ys0<<<dim3(TT, HH / 64), 256>>>();
    k_mma_gemm<<<gemm_grid, 256, GEMM_SMEM>>>(a1h, a1l, nullptr, KP1, KP1 / 32,
                                              w1h, w1l, bih1);
    k_recur_mma<<<128, 512>>>(wh1h, wh1l, bhh1, 1);

    // Head
    k_pool<<<TT, 256>>>(fcW, fcb, out);
}

// round 12
// speedup vs baseline: 1.1219x; 1.1219x over previous
#include <cuda_runtime.h>
#include <cuda_bf16.h>
#include <math.h>
#include <cstdint>
#include <string.h>

// Problem dims
#define TT   512
#define BB   64
#define EE   300
#define HH   512
#define LL   5
#define TH3  1536   // 3*H

#define KP0  320    // padded K for layer-0 input GEMM (E=300 -> 320)
#define KP1  512    // K for layer-1 input GEMM

// ---------------- scratch (device globals; no allocation allowed) -------------
__device__ float g_xp [(size_t)TT * TH3 * BB];   // input projections [T][3H][B]
__device__ float g_ys0[(size_t)TT * HH  * BB];   // layer0 hidden seq [T][H][B]
__device__ float g_ys1[(size_t)TT * HH  * BB];   // layer1 hidden seq [T][H][B]

// split-bf16 (hi+lo) operands for tensor-core GEMMs
__device__ __nv_bfloat16 g_embh[(size_t)30000 * KP0];
__device__ __nv_bfloat16 g_embl[(size_t)30000 * KP0];
__device__ __nv_bfloat16 g_w0h [(size_t)TH3 * KP0];
__device__ __nv_bfloat16 g_w0l [(size_t)TH3 * KP0];
__device__ __nv_bfloat16 g_w1h [(size_t)TH3 * KP1];
__device__ __nv_bfloat16 g_w1l [(size_t)TH3 * KP1];
__device__ __nv_bfloat16 g_a1h [(size_t)TT * BB * KP1];   // ys0 transposed [m=t*64+b][k]
__device__ __nv_bfloat16 g_a1l [(size_t)TT * BB * KP1];

// transposed hidden-state broadcast, fp32: [buf 2][b 64][k 512]
#define HTB (BB * HH)
__device__ float g_hT[(size_t)2 * HTB];

__device__ unsigned g_bar_count = 0;
__device__ unsigned g_bar_sense = 0;

// ======================= helpers (base ISA only; no sm_103a-only ops) =========
__device__ __forceinline__ uint32_t smem_u32(const void* p) {
    uint32_t a;
    asm("{ .reg .u64 t; cvta.to.shared.u64 t, %1; cvt.u32.u64 %0, t; }" : "=r"(a) : "l"(p));
    return a;
}
__device__ __forceinline__ void cp16(uint32_t dst, const void* src) {
    asm volatile("cp.async.cg.shared.global [%0], [%1], 16;" :: "r"(dst), "l"(src));
}
__device__ __forceinline__ void cp_commit() { asm volatile("cp.async.commit_group;" ::: "memory"); }
__device__ __forceinline__ void cp_wait1()  { asm volatile("cp.async.wait_group 1;" ::: "memory"); }
__device__ __forceinline__ void cp_wait0()  { asm volatile("cp.async.wait_group 0;" ::: "memory"); }

__device__ __forceinline__ void mma_bf16(float* c, uint32_t a0, uint32_t a1,
                                         uint32_t a2, uint32_t a3,
                                         uint32_t b0, uint32_t b1) {
    asm volatile(
        "mma.sync.aligned.m16n8k16.row.col.f32.bf16.bf16.f32 "
        "{%0,%1,%2,%3}, {%4,%5,%6,%7}, {%8,%9}, {%0,%1,%2,%3};"
        : "+f"(c[0]), "+f"(c[1]), "+f"(c[2]), "+f"(c[3])
        : "r"(a0), "r"(a1), "r"(a2), "r"(a3), "r"(b0), "r"(b1));
}

// packed fp32x2 FMA: d = a*b + d elementwise on (lo, hi). Base sm_100+ PTX.
__device__ __forceinline__ void fma2(unsigned long long& d, unsigned long long a,
                                     unsigned long long b) {
    asm("fma.rn.f32x2 %0, %1, %2, %0;" : "+l"(d) : "l"(a), "l"(b));
}
__device__ __forceinline__ unsigned long long f2ull(float2 v) {
    unsigned long long u; memcpy(&u, &v, 8); return u;
}
__device__ __forceinline__ float2 ull2f(unsigned long long u) {
    float2 v; memcpy(&v, &u, 8); return v;
}

// =================== conversion kernels (fp32 -> bf16 hi/lo) ==================
__global__ __launch_bounds__(256) void k_conv_pair(
    const float* __restrict__ src, __nv_bfloat16* __restrict__ dh,
    __nv_bfloat16* __restrict__ dl, int N, int Ks, int Kp)
{
    size_t total = (size_t)N * Kp;
    for (size_t idx = (size_t)blockIdx.x * blockDim.x + threadIdx.x; idx < total;
         idx += (size_t)gridDim.x * blockDim.x) {
        int n = (int)(idx / Kp), k = (int)(idx - (size_t)n * Kp);
        float v = (k < Ks) ? src[(size_t)n * Ks + k] : 0.f;
        __nv_bfloat16 hi = __float2bfloat16(v);
        dh[idx] = hi;
        dl[idx] = __float2bfloat16(v - __bfloat162float(hi));
    }
}

// transpose-convert g_ys0 [T][H][B] -> g_a1h/l [m=t*64+b][k=H]
__global__ __launch_bounds__(256) void k_conv_ys0() {
    __shared__ float smt[64][65];
    int t = blockIdx.x, kb = blockIdx.y;     // grid (512, 8)
    const float* src = g_ys0 + ((size_t)t * HH + kb * 64) * BB;
    for (int i = threadIdx.x; i < 4096; i += 256) {
        int k = i >> 6, b = i & 63;
        smt[k][b] = src[(size_t)k * BB + b];
    }
    __syncthreads();
    for (int i = threadIdx.x; i < 4096; i += 256) {
        int b = i >> 6, k = i & 63;
        float v = smt[k][b];
        __nv_bfloat16 hi = __float2bfloat16(v);
        size_t o = ((size_t)t * 64 + b) * KP1 + kb * 64 + k;
        g_a1h[o] = hi;
        g_a1l[o] = __float2bfloat16(v - __bfloat162float(hi));
    }
}

// ============== HMMA split-bf16 GEMM (input projections) ======================
// C[m][n] = sum_k (Ah+Al)[row(m)][k]*(Bh+Bl)[n][k] + bias[n]  (drops Al*Bl).
// CTA 256 thr, tile 128x128, K stage 32, cp.async double buffer.
#define STRD32 20                       // row stride in b32 units
#define TILE_BYTES (128 * 80)           // 10240
#define STAGE_BYTES (4 * TILE_BYTES)    // Ah, Al, Bh, Bl
#define GEMM_SMEM (2 * STAGE_BYTES)     // 81920

__global__ __launch_bounds__(256) void k_mma_gemm(
    const __nv_bfloat16* __restrict__ Ah, const __nv_bfloat16* __restrict__ Al,
    const int* __restrict__ rowidx,     // null => identity (row = m)
    int Kpad, int S,
    const __nv_bfloat16* __restrict__ Bh, const __nv_bfloat16* __restrict__ Bl,
    const float* __restrict__ bias)
{
    extern __shared__ __align__(128) char smem[];
    __shared__ int   rows_s[128];
    __shared__ float bias_s[128];

    const int tid = threadIdx.x;
    const int bn = blockIdx.x, bm = blockIdx.y;
    const uint32_t sb = smem_u32(smem);

    if (tid < 128) {
        int m = bm * 128 + tid;
        rows_s[tid] = rowidx ? rowidx[m] : m;
        bias_s[tid] = bias[bn * 128 + tid];
    }
    __syncthreads();

    auto load_stage = [&](int s) {
        uint32_t buf = sb + (uint32_t)(s & 1) * STAGE_BYTES;
        int k0 = s * 32;
#pragma unroll
        for (int i = 0; i < 8; i++) {
            int idx = tid + i * 256;          // 2048 cp16 total
            int tile = idx >> 9;
            int loc = idx & 511;
            int r = loc >> 2, c = loc & 3;
            const __nv_bfloat16* src;
            if (tile < 2) {
                src = (tile == 0 ? Ah : Al) + (size_t)rows_s[r] * Kpad + k0 + c * 8;
            } else {
                src = (tile == 2 ? Bh : Bl) + (size_t)(bn * 128 + r) * Kpad + k0 + c * 8;
            }
            cp16(buf + tile * TILE_BYTES + r * 80 + c * 16, src);
        }
        cp_commit();
    };

    load_stage(0);
    if (S > 1) load_stage(1);

    const int wid = tid >> 5, lane = tid & 31;
    const int wm = wid & 3, wn = wid >> 2;
    const int g = lane >> 2, q = lane & 3;

    float acc[2][8][4];
#pragma unroll
    for (int mt = 0; mt < 2; mt++)
#pragma unroll
        for (int nt = 0; nt < 8; nt++)
#pragma unroll
            for (int e = 0; e < 4; e++) acc[mt][nt][e] = 0.f;

    for (int s = 0; s < S; s++) {
        if (s + 1 < S) cp_wait1(); else cp_wait0();
        __syncthreads();
        const char* buf = smem + (size_t)(s & 1) * STAGE_BYTES;
        const uint32_t* Ah32 = (const uint32_t*)(buf);
        const uint32_t* Al32 = (const uint32_t*)(buf + TILE_BYTES);
        const uint32_t* Bh32 = (const uint32_t*)(buf + 2 * TILE_BYTES);
        const uint32_t* Bl32 = (const uint32_t*)(buf + 3 * TILE_BYTES);

#pragma unroll
        for (int kh = 0; kh < 2; kh++) {
            const int kb = kh * 8;
            uint32_t ah[2][4], al[2][4];
#pragma unroll
            for (int mt = 0; mt < 2; mt++) {
                int r0 = (wm * 32 + mt * 16 + g) * STRD32;
                int r1 = r0 + 8 * STRD32;
                ah[mt][0] = Ah32[r0 + kb + q];
                ah[mt][1] = Ah32[r1 + kb + q];
                ah[mt][2] = Ah32[r0 + kb + q + 4];
                ah[mt][3] = Ah32[r1 + kb + q + 4];
                al[mt][0] = Al32[r0 + kb + q];
                al[mt][1] = Al32[r1 + kb + q];
                al[mt][2] = Al32[r0 + kb + q + 4];
                al[mt][3] = Al32[r1 + kb + q + 4];
            }
#pragma unroll
            for (int nt = 0; nt < 8; nt++) {
                int nr = (wn * 64 + nt * 8 + g) * STRD32;
                uint32_t bh0 = Bh32[nr + kb + q];
                uint32_t bh1 = Bh32[nr + kb + q + 4];
                uint32_t bl0 = Bl32[nr + kb + q];
                uint32_t bl1 = Bl32[nr + kb + q + 4];
#pragma unroll
                for (int mt = 0; mt < 2; mt++) {
                    mma_bf16(acc[mt][nt], ah[mt][0], ah[mt][1], ah[mt][2], ah[mt][3], bh0, bh1);
                    mma_bf16(acc[mt][nt], ah[mt][0], ah[mt][1], ah[mt][2], ah[mt][3], bl0, bl1);
                    mma_bf16(acc[mt][nt], al[mt][0], al[mt][1], al[mt][2], al[mt][3], bh0, bh1);
                }
            }
        }
        __syncthreads();
        if (s + 2 < S) load_stage(s + 2);
    }

#pragma unroll
    for (int mt = 0; mt < 2; mt++) {
        int r0 = wm * 32 + mt * 16 + g;
        int m0 = bm * 128 + r0;
        int m1 = m0 + 8;
        float* p0 = g_xp + ((size_t)(m0 >> 6) * TH3) * BB + (m0 & 63);
        float* p1 = g_xp + ((size_t)(m1 >> 6) * TH3) * BB + (m1 & 63);
#pragma unroll
        for (int nt = 0; nt < 8; nt++) {
            int c = wn * 64 + nt * 8 + q * 2;
            int n0 = bn * 128 + c;
            float bv0 = bias_s[c], bv1 = bias_s[c + 1];
            p0[(size_t)n0 * BB]       = acc[mt][nt][0] + bv0;
            p0[(size_t)(n0 + 1) * BB] = acc[mt][nt][1] + bv1;
            p1[(size_t)n0 * BB]       = acc[mt][nt][2] + bv0;
            p1[(size_t)(n0 + 1) * BB] = acc[mt][nt][3] + bv1;
        }
    }
}

// ========== persistent GRU recurrence, packed FFMA2 + k-split (one layer) =====
// Grid 128 CTAs x 512 thr. CTA owns 4 hidden cols j (12 Whh gate rows in SMEM).
// Warp w owns k-slice [32w, 32w+32) for ALL 12 rows; lane covers b={2l, 2l+1}.
// h(t-1) read from g_hT[buf][b][k] (fp32, [b][k] layout -> contiguous k pairs).
// Packed fp32x2 over (k even, k odd): W pair = 1 LDS.64, h pair = half a LDG.128.
__device__ __forceinline__ float fsigm(float x) {
    return __fdividef(1.f, 1.f + __expf(-x));
}
__device__ __forceinline__ float ftanh(float x) {
    return 1.f - __fdividef(2.f, 1.f + __expf(2.f * x));
}

#define RC_WS_F   (12 * 512)
#define RC_RED_F  (16 * 12 * 64)
#define RC_HROW_F (4 * 64)
#define RC_SMEM   ((RC_WS_F + RC_RED_F + RC_HROW_F + 16) * 4)

__global__ __launch_bounds__(512, 1) void k_recur(
    const float* __restrict__ Whh,   // [3H][H]
    const float* __restrict__ bhh,   // [3H]
    int layer)
{
    extern __shared__ __align__(16) float rs[];
    float* Ws    = rs;                          // [12][512]
    float* red   = rs + RC_WS_F;                // [16 warps][12 rows][64 b]
    float* hrow  = rs + RC_WS_F + RC_RED_F;     // [4][64]
    float* bhh_s = hrow + RC_HROW_F;            // [12]

    float* __restrict__ ys = layer ? g_ys1 : g_ys0;
    const float* __restrict__ xp = g_xp;

    const int tid   = threadIdx.x;
    const int jbase = blockIdx.x * 4;
    const int nb    = gridDim.x;

    // load Whh gate rows: local row lr = g*4+jl -> global row g*H + jbase + jl
    for (int idx = tid; idx < 12 * 512; idx += 512) {
        int lr = idx >> 9, k = idx & 511;
        int g = lr >> 2, jl = lr & 3;
        Ws[idx] = Whh[((size_t)(g * HH + jbase + jl)) * HH + k];
    }
    if (tid < 12) {
        int g = tid >> 2, jl = tid & 3;
        bhh_s[tid] = bhh[g * HH + jbase + jl];
    }
    __syncthreads();

    const int warp  = tid >> 5;
    const int lane  = tid & 31;
    const int kbase = warp * 32;                // this warp's k-slice
    const float2* Ws2 = (const float2*)Ws;      // [12][256] k-pairs

    // tail-thread persistent state (tid < 256)
    const int rjl = tid >> 6, rb = tid & 63;
    float hq = 0.f;

    unsigned lsense = 0;

    for (int t = 0; t < TT; t++) {
        // ---- xp prefetch (overlaps barrier wait) ----
        float xr = 0.f, xz = 0.f, xn = 0.f;
        if (tid < 256) {
            const float* xpb = xp + (size_t)t * TH3 * BB + rb;
            int j = jbase + rjl;
            xr = __ldcg(xpb + (size_t)(0 * HH + j) * BB);
            xz = __ldcg(xpb + (size_t)(1 * HH + j) * BB);
            xn = __ldcg(xpb + (size_t)(2 * HH + j) * BB);
        }

        if (t > 0) {
            // ---- barrier wait (arrive was at end of previous step) ----
            if (tid == 0) {
                volatile unsigned* vs = &g_bar_sense;
                while (*vs != lsense) { __nanosleep(32); }
                __threadfence();
            }
            __syncthreads();

            // ---- matvec: acc[row][b01] over k-slice, packed (k even, k odd) ----
            const float* hb0 = g_hT + (size_t)((t - 1) & 1) * HTB
                             + (size_t)(2 * lane) * HH + kbase;
            const float* hb1 = hb0 + HH;

            unsigned long long acc[12][2];
#pragma unroll
            for (int r = 0; r < 12; r++) { acc[r][0] = 0ull; acc[r][1] = 0ull; }

#pragma unroll
            for (int c = 0; c < 8; c++) {       // 8 chunks x 4 k
                ulonglong2 va = __ldcg((const ulonglong2*)(hb0 + c * 4));
                ulonglong2 vb = __ldcg((const ulonglong2*)(hb1 + c * 4));
                const int kp = (kbase >> 1) + c * 2;
#pragma unroll
                for (int r = 0; r < 12; r++) {
                    unsigned long long w0 = f2ull(Ws2[r * 256 + kp]);
                    unsigned long long w1 = f2ull(Ws2[r * 256 + kp + 1]);
                    fma2(acc[r][0], w0, va.x);
                    fma2(acc[r][0], w1, va.y);
                    fma2(acc[r][1], w0, vb.x);
                    fma2(acc[r][1], w1, vb.y);
                }
            }
            // fold (even,odd) halves and write partials
            float2* redv = (float2*)red;
#pragma unroll
            for (int r = 0; r < 12; r++) {
                float2 f0 = ull2f(acc[r][0]);
                float2 f1 = ull2f(acc[r][1]);
                redv[(warp * 12 + r) * 32 + lane] =
                    make_float2(f0.x + f0.y, f1.x + f1.y);
            }
        }
        __syncthreads();

        // ---- tail: reduce 16 warps, gates, h update ----
        if (tid < 256) {
            float s0 = bhh_s[0 + rjl];
            float s1 = bhh_s[4 + rjl];
            float s2 = bhh_s[8 + rjl];
            if (t > 0) {
#pragma unroll
                for (int w = 0; w < 16; w++) {
                    s0 += red[(w * 12 + 0 + rjl) * 64 + rb];
                    s1 += red[(w * 12 + 4 + rjl) * 64 + rb];
                    s2 += red[(w * 12 + 8 + rjl) * 64 + rb];
                }
            }
            float r = fsigm(xr + s0);
            float z = fsigm(xz + s1);
            float n = ftanh(xn + r * s2);
            float hnew = (1.f - z) * n + z * hq;
            hq = hnew;

            ys[((size_t)t * HH + (jbase + rjl)) * BB + rb] = hnew;
            hrow[rjl * 64 + rb] = hnew;
        }
        __syncthreads();

        // ---- publish h(t) to g_hT[t&1][b][jbase..jbase+3] (float4/row) ----
        if (tid < 64) {
            float4 v = make_float4(hrow[0 * 64 + tid], hrow[1 * 64 + tid],
                                   hrow[2 * 64 + tid], hrow[3 * 64 + tid]);
            *(float4*)(g_hT + (size_t)(t & 1) * HTB + (size_t)tid * HH + jbase) = v;
        }
        __syncthreads();

        // ---- barrier arrive ----
        if (tid == 0) {
            unsigned s = lsense ^ 1u;
            __threadfence();
            if (atomicAdd(&g_bar_count, 1u) == (unsigned)(nb - 1)) {
                g_bar_count = 0u;
                __threadfence();
                atomicExch(&g_bar_sense, s);
            }
        }
        lsense ^= 1u;
    }
}

// ==================== mean over batch + FC head ===============================
__global__ __launch_bounds__(256) void k_pool(
    const float* __restrict__ fcW,
    const float* __restrict__ fcb,
    float*       __restrict__ out)
{
    int t = blockIdx.x;
    const float* base = g_ys1 + (size_t)t * HH * BB;
    int w = threadIdx.x >> 5, l = threadIdx.x & 31;

    float acc[LL];
#pragma unroll
    for (int j = 0; j < LL; j++) acc[j] = 0.f;

    for (int h = w; h < HH; h += 8) {
        float s = base[h * BB + l] + base[h * BB + 32 + l];
#pragma unroll
        for (int off = 16; off >= 1; off >>= 1)
            s += __shfl_xor_sync(0xffffffffu, s, off);
        if (l == 0) {
            float p = s * (1.f / 64.f);
#pragma unroll
            for (int j = 0; j < LL; j++) acc[j] = fmaf(p, fcW[j * HH + h], acc[j]);
        }
    }
    __shared__ float sred[8][LL];
    if (l == 0) {
#pragma unroll
        for (int j = 0; j < LL; j++) sred[w][j] = acc[j];
    }
    __syncthreads();
    if (threadIdx.x < LL) {
        float s = fcb[threadIdx.x];
#pragma unroll
        for (int ww = 0; ww < 8; ww++) s += sred[ww][threadIdx.x];
        out[t * LL + threadIdx.x] = s;
    }
}

// ============================== launch ========================================
extern "C" void kernel_launch(void* const* d_in, const int* in_sizes, int n_in,
                              void* d_out, int out_size) {
    const int*   texts = (const int*)  d_in[0];
    const float* emb   = (const float*)d_in[1];
    const float* Wih0  = (const float*)d_in[2];
    const float* Whh0  = (const float*)d_in[3];
    const float* bih0  = (const float*)d_in[4];
    const float* bhh0  = (const float*)d_in[5];
    const float* Wih1  = (const float*)d_in[6];
    const float* Whh1  = (const float*)d_in[7];
    const float* bih1  = (const float*)d_in[8];
    const float* bhh1  = (const float*)d_in[9];
    const float* fcW   = (const float*)d_in[10];
    const float* fcb   = (const float*)d_in[11];
    float* out = (float*)d_out;

    cudaFuncSetAttribute(k_mma_gemm, cudaFuncAttributeMaxDynamicSharedMemorySize,
                         GEMM_SMEM);
    cudaFuncSetAttribute(k_recur, cudaFuncAttributeMaxDynamicSharedMemorySize,
                         RC_SMEM);

    // resolve device-global scratch addresses for kernel params
    __nv_bfloat16 *embh, *embl, *w0h, *w0l, *w1h, *w1l, *a1h, *a1l;
    cudaGetSymbolAddress((void**)&embh, g_embh);
    cudaGetSymbolAddress((void**)&embl, g_embl);
    cudaGetSymbolAddress((void**)&w0h,  g_w0h);
    cudaGetSymbolAddress((void**)&w0l,  g_w0l);
    cudaGetSymbolAddress((void**)&w1h,  g_w1h);
    cudaGetSymbolAddress((void**)&w1l,  g_w1l);
    cudaGetSymbolAddress((void**)&a1h,  g_a1h);
    cudaGetSymbolAddress((void**)&a1l,  g_a1l);

    dim3 gemm_grid(TH3 / 128, (TT * BB) / 128);   // (12, 256)

    // conversions (static operands)
    k_conv_pair<<<8192, 256>>>(emb,  embh, embl, 30000, EE, KP0);
    k_conv_pair<<<1024, 256>>>(Wih0, w0h,  w0l,  TH3,   EE, KP0);
    k_conv_pair<<<1024, 256>>>(Wih1, w1h,  w1l,  TH3,   HH, KP1);

    // Layer 0: xp = emb[texts] @ Wih0^T + bih0 (HMMA), then recurrence
    k_mma_gemm<<<gemm_grid, 256, GEMM_SMEM>>>(embh, embl, texts, KP0, KP0 / 32,
                                              w0h, w0l, bih0);
    k_recur<<<128, 512, RC_SMEM>>>(Whh0, bhh0, 0);

    // Layer 1: transpose-convert ys0, xp = ys0 @ Wih1^T + bih1, recurrence
    k_conv_ys0<<<dim3(TT, HH / 64), 256>>>();
    k_mma_gemm<<<gemm_grid, 256, GEMM_SMEM>>>(a1h, a1l, nullptr, KP1, KP1 / 32,
                                              w1h, w1l, bih1);
    k_recur<<<128, 512, RC_SMEM>>>(Whh1, bhh1, 1);

    // Head
    k_pool<<<TT, 256>>>(fcW, fcb, out);
}

// round 13
// speedup vs baseline: 1.2208x; 1.0881x over previous
#include <cuda_runtime.h>
#include <cuda_bf16.h>
#include <math.h>
#include <cstdint>

// Problem dims
#define TT   512
#define BB   64
#define EE   300
#define HH   512
#define LL   5
#define TH3  1536   // 3*H

#define KP0  320    // padded K for layer-0 input GEMM (E=300 -> 320)
#define KP1  512    // K for layer-1 input GEMM

// ---------------- scratch (device globals; no allocation allowed) -------------
__device__ float g_xp [(size_t)TT * TH3 * BB];   // input projections [T][3H][B]
__device__ float g_ys0[(size_t)TT * HH  * BB];   // layer0 hidden seq [T][H][B]
__device__ float g_ys1[(size_t)TT * HH  * BB];   // layer1 hidden seq [T][H][B]

// split-bf16 (hi+lo) operands for tensor-core GEMMs
__device__ __nv_bfloat16 g_embh[(size_t)30000 * KP0];
__device__ __nv_bfloat16 g_embl[(size_t)30000 * KP0];
__device__ __nv_bfloat16 g_w0h [(size_t)TH3 * KP0];
__device__ __nv_bfloat16 g_w0l [(size_t)TH3 * KP0];
__device__ __nv_bfloat16 g_w1h [(size_t)TH3 * KP1];
__device__ __nv_bfloat16 g_w1l [(size_t)TH3 * KP1];
__device__ __nv_bfloat16 g_a1h [(size_t)TT * BB * KP1];   // ys0 transposed [m=t*64+b][k]
__device__ __nv_bfloat16 g_a1l [(size_t)TT * BB * KP1];

// two-level grid barrier state (self-resetting; zero at launch start/end)
__device__ unsigned g_leaf[16 * 32];   // one counter per 128B line
__device__ unsigned g_root = 0;
__device__ unsigned g_bar_sense = 0;

// ======================= helpers (base ISA only; no sm_103a-only ops) =========
__device__ __forceinline__ uint32_t smem_u32(const void* p) {
    uint32_t a;
    asm("{ .reg .u64 t; cvta.to.shared.u64 t, %1; cvt.u32.u64 %0, t; }" : "=r"(a) : "l"(p));
    return a;
}
__device__ __forceinline__ void cp16(uint32_t dst, const void* src) {
    asm volatile("cp.async.cg.shared.global [%0], [%1], 16;" :: "r"(dst), "l"(src));
}
__device__ __forceinline__ void cp_commit() { asm volatile("cp.async.commit_group;" ::: "memory"); }
__device__ __forceinline__ void cp_wait1()  { asm volatile("cp.async.wait_group 1;" ::: "memory"); }
__device__ __forceinline__ void cp_wait0()  { asm volatile("cp.async.wait_group 0;" ::: "memory"); }

__device__ __forceinline__ void mma_bf16(float* c, uint32_t a0, uint32_t a1,
                                         uint32_t a2, uint32_t a3,
                                         uint32_t b0, uint32_t b1) {
    asm volatile(
        "mma.sync.aligned.m16n8k16.row.col.f32.bf16.bf16.f32 "
        "{%0,%1,%2,%3}, {%4,%5,%6,%7}, {%8,%9}, {%0,%1,%2,%3};"
        : "+f"(c[0]), "+f"(c[1]), "+f"(c[2]), "+f"(c[3])
        : "r"(a0), "r"(a1), "r"(a2), "r"(a3), "r"(b0), "r"(b1));
}

// =================== conversion kernels (fp32 -> bf16 hi/lo) ==================
__global__ __launch_bounds__(256) void k_conv_pair(
    const float* __restrict__ src, __nv_bfloat16* __restrict__ dh,
    __nv_bfloat16* __restrict__ dl, int N, int Ks, int Kp)
{
    size_t total = (size_t)N * Kp;
    for (size_t idx = (size_t)blockIdx.x * blockDim.x + threadIdx.x; idx < total;
         idx += (size_t)gridDim.x * blockDim.x) {
        int n = (int)(idx / Kp), k = (int)(idx - (size_t)n * Kp);
        float v = (k < Ks) ? src[(size_t)n * Ks + k] : 0.f;
        __nv_bfloat16 hi = __float2bfloat16(v);
        dh[idx] = hi;
        dl[idx] = __float2bfloat16(v - __bfloat162float(hi));
    }
}

// ============== HMMA split-bf16 GEMM (input projections) ======================
// C[m][n] = sum_k (Ah+Al)[row(m)][k]*(Bh+Bl)[n][k] + bias[n]  (drops Al*Bl).
// CTA 256 thr, tile 128x128, K stage 32, cp.async double buffer.
#define STRD32 20                       // row stride in b32 units
#define TILE_BYTES (128 * 80)           // 10240
#define STAGE_BYTES (4 * TILE_BYTES)    // Ah, Al, Bh, Bl
#define GEMM_SMEM (2 * STAGE_BYTES)     // 81920

__global__ __launch_bounds__(256) void k_mma_gemm(
    const __nv_bfloat16* __restrict__ Ah, const __nv_bfloat16* __restrict__ Al,
    const int* __restrict__ rowidx,     // null => identity (row = m)
    int Kpad, int S,
    const __nv_bfloat16* __restrict__ Bh, const __nv_bfloat16* __restrict__ Bl,
    const float* __restrict__ bias)
{
    extern __shared__ __align__(128) char smem[];
    __shared__ int   rows_s[128];
    __shared__ float bias_s[128];

    const int tid = threadIdx.x;
    const int bn = blockIdx.x, bm = blockIdx.y;
    const uint32_t sb = smem_u32(smem);

    if (tid < 128) {
        int m = bm * 128 + tid;
        rows_s[tid] = rowidx ? rowidx[m] : m;
        bias_s[tid] = bias[bn * 128 + tid];
    }
    __syncthreads();

    auto load_stage = [&](int s) {
        uint32_t buf = sb + (uint32_t)(s & 1) * STAGE_BYTES;
        int k0 = s * 32;
#pragma unroll
        for (int i = 0; i < 8; i++) {
            int idx = tid + i * 256;          // 2048 cp16 total
            int tile = idx >> 9;
            int loc = idx & 511;
            int r = loc >> 2, c = loc & 3;
            const __nv_bfloat16* src;
            if (tile < 2) {
                src = (tile == 0 ? Ah : Al) + (size_t)rows_s[r] * Kpad + k0 + c * 8;
            } else {
                src = (tile == 2 ? Bh : Bl) + (size_t)(bn * 128 + r) * Kpad + k0 + c * 8;
            }
            cp16(buf + tile * TILE_BYTES + r * 80 + c * 16, src);
        }
        cp_commit();
    };

    load_stage(0);
    if (S > 1) load_stage(1);

    const int wid = tid >> 5, lane = tid & 31;
    const int wm = wid & 3, wn = wid >> 2;
    const int g = lane >> 2, q = lane & 3;

    float acc[2][8][4];
#pragma unroll
    for (int mt = 0; mt < 2; mt++)
#pragma unroll
        for (int nt = 0; nt < 8; nt++)
#pragma unroll
            for (int e = 0; e < 4; e++) acc[mt][nt][e] = 0.f;

    for (int s = 0; s < S; s++) {
        if (s + 1 < S) cp_wait1(); else cp_wait0();
        __syncthreads();
        const char* buf = smem + (size_t)(s & 1) * STAGE_BYTES;
        const uint32_t* Ah32 = (const uint32_t*)(buf);
        const uint32_t* Al32 = (const uint32_t*)(buf + TILE_BYTES);
        const uint32_t* Bh32 = (const uint32_t*)(buf + 2 * TILE_BYTES);
        const uint32_t* Bl32 = (const uint32_t*)(buf + 3 * TILE_BYTES);

#pragma unroll
        for (int kh = 0; kh < 2; kh++) {
            const int kb = kh * 8;
            uint32_t ah[2][4], al[2][4];
#pragma unroll
            for (int mt = 0; mt < 2; mt++) {
                int r0 = (wm * 32 + mt * 16 + g) * STRD32;
                int r1 = r0 + 8 * STRD32;
                ah[mt][0] = Ah32[r0 + kb + q];
                ah[mt][1] = Ah32[r1 + kb + q];
                ah[mt][2] = Ah32[r0 + kb + q + 4];
                ah[mt][3] = Ah32[r1 + kb + q + 4];
                al[mt][0] = Al32[r0 + kb + q];
                al[mt][1] = Al32[r1 + kb + q];
                al[mt][2] = Al32[r0 + kb + q + 4];
                al[mt][3] = Al32[r1 + kb + q + 4];
            }
#pragma unroll
            for (int nt = 0; nt < 8; nt++) {
                int nr = (wn * 64 + nt * 8 + g) * STRD32;
                uint32_t bh0 = Bh32[nr + kb + q];
                uint32_t bh1 = Bh32[nr + kb + q + 4];
                uint32_t bl0 = Bl32[nr + kb + q];
                uint32_t bl1 = Bl32[nr + kb + q + 4];
#pragma unroll
                for (int mt = 0; mt < 2; mt++) {
                    mma_bf16(acc[mt][nt], ah[mt][0], ah[mt][1], ah[mt][2], ah[mt][3], bh0, bh1);
                    mma_bf16(acc[mt][nt], ah[mt][0], ah[mt][1], ah[mt][2], ah[mt][3], bl0, bl1);
                    mma_bf16(acc[mt][nt], al[mt][0], al[mt][1], al[mt][2], al[mt][3], bh0, bh1);
                }
            }
        }
        __syncthreads();
        if (s + 2 < S) load_stage(s + 2);
    }

#pragma unroll
    for (int mt = 0; mt < 2; mt++) {
        int r0 = wm * 32 + mt * 16 + g;
        int m0 = bm * 128 + r0;
        int m1 = m0 + 8;
        float* p0 = g_xp + ((size_t)(m0 >> 6) * TH3) * BB + (m0 & 63);
        float* p1 = g_xp + ((size_t)(m1 >> 6) * TH3) * BB + (m1 & 63);
#pragma unroll
        for (int nt = 0; nt < 8; nt++) {
            int c = wn * 64 + nt * 8 + q * 2;
            int n0 = bn * 128 + c;
            float bv0 = bias_s[c], bv1 = bias_s[c + 1];
            p0[(size_t)n0 * BB]       = acc[mt][nt][0] + bv0;
            p0[(size_t)(n0 + 1) * BB] = acc[mt][nt][1] + bv1;
            p1[(size_t)n0 * BB]       = acc[mt][nt][2] + bv0;
            p1[(size_t)(n0 + 1) * BB] = acc[mt][nt][3] + bv1;
        }
    }
}

// ==================== persistent GRU recurrence (one layer) ===================
// Grid 128 CTAs x 512 thr. CTA owns 4 hidden cols j (12 Whh rows in SMEM).
// Warp w: jl=w&3 (which j), ksec=w>>2 (K/4 slice). Lane covers b={2l,2l+1}.
// h loads register-pipelined 3 k4-iterations ahead to hide L2 latency.
__device__ __forceinline__ float fsigm(float x) {
    return __fdividef(1.f, 1.f + __expf(-x));
}
__device__ __forceinline__ float ftanh(float x) {
    return 1.f - __fdividef(2.f, 1.f + __expf(2.f * x));
}

__global__ __launch_bounds__(512, 1) void k_recur(
    const float* __restrict__ Whh,   // [3H][H]
    const float* __restrict__ bhh,   // [3H]
    int layer)
{
    __shared__ __align__(16) float Ws[12 * 512];
    __shared__ __align__(16) float red[4 * 4 * 3 * 64];   // [ksec][jl][gate][b]
    __shared__ float bhh_s[12];

    float* __restrict__ ys = layer ? g_ys1 : g_ys0;
    const float* __restrict__ xp = g_xp;

    const int tid   = threadIdx.x;
    const int jbase = blockIdx.x * 4;

    for (int idx = tid; idx < 12 * 512; idx += 512) {
        int lr = idx >> 9, k = idx & 511;
        int g = lr >> 2, jl = lr & 3;
        Ws[idx] = Whh[((size_t)(g * HH + jbase + jl)) * HH + k];
    }
    if (tid < 12) {
        int g = tid >> 2, jl = tid & 3;
        bhh_s[tid] = bhh[g * HH + jbase + jl];
    }
    __syncthreads();

    const int warp = tid >> 5;
    const int lane = tid & 31;
    const int jl   = warp & 3;
    const int ksec = warp >> 2;
    const int kbase = ksec * 128;

    const float* w0 = Ws + (0 * 4 + jl) * 512 + kbase;
    const float* w1 = Ws + (1 * 4 + jl) * 512 + kbase;
    const float* w2 = Ws + (2 * 4 + jl) * 512 + kbase;

    // tail-thread persistent state (tid < 256)
    const int rjl = tid >> 6, rb = tid & 63;
    float hq = 0.f;

    for (int t = 0; t < TT; t++) {
        // ---- xp prefetch (overlaps barrier spin below) ----
        float xr = 0.f, xz = 0.f, xn = 0.f;
        if (tid < 256) {
            const float* xpb = xp + (size_t)t * TH3 * BB + rb;
            int j = jbase + rjl;
            xr = __ldcg(xpb + (size_t)(0 * HH + j) * BB);
            xz = __ldcg(xpb + (size_t)(1 * HH + j) * BB);
            xn = __ldcg(xpb + (size_t)(2 * HH + j) * BB);
        }

        if (t > 0) {
            // ---- wait for step t-1 completion (arrive happened at its end) ----
            if (tid == 0) {
                volatile unsigned* vs = &g_bar_sense;
                unsigned want = (unsigned)(t & 1);
                while (*vs != want) { __nanosleep(32); }
                __threadfence();
            }
            __syncthreads();

            // ---- matvec over this warp's 128-k slice, 3-ahead load pipeline ---
            const float* hb = ys + ((size_t)(t - 1) * HH + kbase) * BB + 2 * lane;
            float2 hbuf[3][4];
#pragma unroll
            for (int p = 0; p < 3; p++) {
                const float* s = hb + p * 4 * BB;
                hbuf[p][0] = __ldcg((const float2*)(s));
                hbuf[p][1] = __ldcg((const float2*)(s + BB));
                hbuf[p][2] = __ldcg((const float2*)(s + 2 * BB));
                hbuf[p][3] = __ldcg((const float2*)(s + 3 * BB));
            }

            float a00 = 0.f, a01 = 0.f, a10 = 0.f, a11 = 0.f, a20 = 0.f, a21 = 0.f;
#pragma unroll
            for (int k4 = 0; k4 < 32; k4++) {
                const int slot = k4 % 3;
                float2 h0 = hbuf[slot][0];
                float2 h1 = hbuf[slot][1];
                float2 h2 = hbuf[slot][2];
                float2 h3 = hbuf[slot][3];
                if (k4 + 3 < 32) {
                    const float* s = hb + (k4 + 3) * 4 * BB;
                    hbuf[slot][0] = __ldcg((const float2*)(s));
                    hbuf[slot][1] = __ldcg((const float2*)(s + BB));
                    hbuf[slot][2] = __ldcg((const float2*)(s + 2 * BB));
                    hbuf[slot][3] = __ldcg((const float2*)(s + 3 * BB));
                }
                float4 wa = *(const float4*)(w0 + k4 * 4);
                float4 wb = *(const float4*)(w1 + k4 * 4);
                float4 wc = *(const float4*)(w2 + k4 * 4);
                a00 = fmaf(wa.x, h0.x, fmaf(wa.y, h1.x, fmaf(wa.z, h2.x, fmaf(wa.w, h3.x, a00))));
                a01 = fmaf(wa.x, h0.y, fmaf(wa.y, h1.y, fmaf(wa.z, h2.y, fmaf(wa.w, h3.y, a01))));
                a10 = fmaf(wb.x, h0.x, fmaf(wb.y, h1.x, fmaf(wb.z, h2.x, fmaf(wb.w, h3.x, a10))));
                a11 = fmaf(wb.x, h0.y, fmaf(wb.y, h1.y, fmaf(wb.z, h2.y, fmaf(wb.w, h3.y, a11))));
                a20 = fmaf(wc.x, h0.x, fmaf(wc.y, h1.x, fmaf(wc.z, h2.x, fmaf(wc.w, h3.x, a20))));
                a21 = fmaf(wc.x, h0.y, fmaf(wc.y, h1.y, fmaf(wc.z, h2.y, fmaf(wc.w, h3.y, a21))));
            }
            int rbi = ((ksec * 4 + jl) * 3 + 0) * 64 + 2 * lane;
            red[rbi]       = a00; red[rbi + 1]   = a01;
            red[rbi + 64]  = a10; red[rbi + 65]  = a11;
            red[rbi + 128] = a20; red[rbi + 129] = a21;
        }
        __syncthreads();

        // ---- tail: reduce 4 ksec partials, gates, h update ----
        if (tid < 256) {
            float s0 = bhh_s[0 + rjl];
            float s1 = bhh_s[4 + rjl];
            float s2 = bhh_s[8 + rjl];
            if (t > 0) {
#pragma unroll
                for (int ks = 0; ks < 4; ks++) {
                    int base = ((ks * 4 + rjl) * 3) * 64 + rb;
                    s0 += red[base];
                    s1 += red[base + 64];
                    s2 += red[base + 128];
                }
            }
            float r = fsigm(xr + s0);
            float z = fsigm(xz + s1);
            float n = ftanh(xn + r * s2);
            float hnew = (1.f - z) * n + z * hq;
            hq = hnew;

            int j = jbase + rjl;
            ys[((size_t)t * HH + j) * BB + rb] = hnew;

            // layer 0: fuse the transpose + bf16 hi/lo convert for layer-1 GEMM
            if (layer == 0) {
                __nv_bfloat16 hi = __float2bfloat16(hnew);
                __nv_bfloat16 lo = __float2bfloat16(hnew - __bfloat162float(hi));
                size_t o = ((size_t)t * 64 + rb) * KP1 + j;
                g_a1h[o] = hi;
                g_a1l[o] = lo;
            }
        }
        __syncthreads();

        // ---- two-level barrier arrive (wait happens at next step's start) ----
        if (tid == 0) {
            __threadfence();
            unsigned leaf = (blockIdx.x & 15u) * 32u;
            if (atomicAdd(&g_leaf[leaf], 1u) == 7u) {
                g_leaf[leaf] = 0u;
                __threadfence();
                if (atomicAdd(&g_root, 1u) == 15u) {
                    g_root = 0u;
                    __threadfence();
                    atomicExch(&g_bar_sense, (unsigned)((t + 1) & 1));
                }
            }
        }
    }
}

// ==================== mean over batch + FC head ===============================
__global__ __launch_bounds__(256) void k_pool(
    const float* __restrict__ fcW,
    const float* __restrict__ fcb,
    float*       __restrict__ out)
{
    int t = blockIdx.x;
    const float* base = g_ys1 + (size_t)t * HH * BB;
    int w = threadIdx.x >> 5, l = threadIdx.x & 31;

    float acc[LL];
#pragma unroll
    for (int j = 0; j < LL; j++) acc[j] = 0.f;

    for (int h = w; h < HH; h += 8) {
        float s = base[h * BB + l] + base[h * BB + 32 + l];
#pragma unroll
        for (int off = 16; off >= 1; off >>= 1)
            s += __shfl_xor_sync(0xffffffffu, s, off);
        if (l == 0) {
            float p = s * (1.f / 64.f);
#pragma unroll
            for (int j = 0; j < LL; j++) acc[j] = fmaf(p, fcW[j * HH + h], acc[j]);
        }
    }
    __shared__ float sred[8][LL];
    if (l == 0) {
#pragma unroll
        for (int j = 0; j < LL; j++) sred[w][j] = acc[j];
    }
    __syncthreads();
    if (threadIdx.x < LL) {
        float s = fcb[threadIdx.x];
#pragma unroll
        for (int ww = 0; ww < 8; ww++) s += sred[ww][threadIdx.x];
        out[t * LL + threadIdx.x] = s;
    }
}

// ============================== launch ========================================
extern "C" void kernel_launch(void* const* d_in, const int* in_sizes, int n_in,
                              void* d_out, int out_size) {
    const int*   texts = (const int*)  d_in[0];
    const float* emb   = (const float*)d_in[1];
    const float* Wih0  = (const float*)d_in[2];
    const float* Whh0  = (const float*)d_in[3];
    const float* bih0  = (const float*)d_in[4];
    const float* bhh0  = (const float*)d_in[5];
    const float* Wih1  = (const float*)d_in[6];
    const float* Whh1  = (const float*)d_in[7];
    const float* bih1  = (const float*)d_in[8];
    const float* bhh1  = (const float*)d_in[9];
    const float* fcW   = (const float*)d_in[10];
    const float* fcb   = (const float*)d_in[11];
    float* out = (float*)d_out;

    cudaFuncSetAttribute(k_mma_gemm, cudaFuncAttributeMaxDynamicSharedMemorySize,
                         GEMM_SMEM);

    // resolve device-global scratch addresses for kernel params
    __nv_bfloat16 *embh, *embl, *w0h, *w0l, *w1h, *w1l, *a1h, *a1l;
    cudaGetSymbolAddress((void**)&embh, g_embh);
    cudaGetSymbolAddress((void**)&embl, g_embl);
    cudaGetSymbolAddress((void**)&w0h,  g_w0h);
    cudaGetSymbolAddress((void**)&w0l,  g_w0l);
    cudaGetSymbolAddress((void**)&w1h,  g_w1h);
    cudaGetSymbolAddress((void**)&w1l,  g_w1l);
    cudaGetSymbolAddress((void**)&a1h,  g_a1h);
    cudaGetSymbolAddress((void**)&a1l,  g_a1l);

    dim3 gemm_grid(TH3 / 128, (TT * BB) / 128);   // (12, 256)

    // conversions (static operands)
    k_conv_pair<<<8192, 256>>>(emb,  embh, embl, 30000, EE, KP0);
    k_conv_pair<<<1024, 256>>>(Wih0, w0h,  w0l,  TH3,   EE, KP0);
    k_conv_pair<<<1024, 256>>>(Wih1, w1h,  w1l,  TH3,   HH, KP1);

    // Layer 0: xp = emb[texts] @ Wih0^T + bih0 (HMMA), then recurrence
    // (recurrence also emits a1h/a1l for the layer-1 GEMM)
    k_mma_gemm<<<gemm_grid, 256, GEMM_SMEM>>>(embh, embl, texts, KP0, KP0 / 32,
                                              w0h, w0l, bih0);
    k_recur<<<128, 512>>>(Whh0, bhh0, 0);

    // Layer 1: xp = ys0 @ Wih1^T + bih1 (HMMA), then recurrence
    k_mma_gemm<<<gemm_grid, 256, GEMM_SMEM>>>(a1h, a1l, nullptr, KP1, KP1 / 32,
                                              w1h, w1l, bih1);
    k_recur<<<128, 512>>>(Whh1, bhh1, 1);

    // Head
    k_pool<<<TT, 256>>>(fcW, fcb, out);
}

// round 14
// speedup vs baseline: 1.3983x; 1.1454x over previous
#include <cuda_runtime.h>
#include <cuda_bf16.h>
#include <math.h>
#include <cstdint>

// Problem dims
#define TT   512
#define BB   64
#define EE   300
#define HH   512
#define LL   5
#define TH3  1536   // 3*H

#define KP0  320    // padded K for layer-0 input GEMM (E=300 -> 320)
#define KP1  512    // K for layer-1 input GEMM

// ---------------- scratch (device globals; no allocation allowed) -------------
__device__ float g_xp [(size_t)TT * TH3 * BB];   // input projections [T][3H][B]
__device__ float g_ys0[(size_t)TT * HH  * BB];   // layer0 hidden seq [T][H][B]
__device__ float g_ys1[(size_t)TT * HH  * BB];   // layer1 hidden seq [T][H][B]

// split-bf16 (hi+lo) operands for tensor-core GEMMs
__device__ __nv_bfloat16 g_embh[(size_t)30000 * KP0];
__device__ __nv_bfloat16 g_embl[(size_t)30000 * KP0];
__device__ __nv_bfloat16 g_w0h [(size_t)TH3 * KP0];
__device__ __nv_bfloat16 g_w0l [(size_t)TH3 * KP0];
__device__ __nv_bfloat16 g_w1h [(size_t)TH3 * KP1];
__device__ __nv_bfloat16 g_w1l [(size_t)TH3 * KP1];
__device__ __nv_bfloat16 g_a1h [(size_t)TT * BB * KP1];   // ys0 transposed [m=t*64+b][k]
__device__ __nv_bfloat16 g_a1l [(size_t)TT * BB * KP1];

// grid barrier state (self-resetting; zero at launch start/end)
__device__ unsigned g_bar_count = 0;
__device__ unsigned g_bar_sense = 0;

// ======================= helpers (base ISA only; no sm_103a-only ops) =========
__device__ __forceinline__ uint32_t smem_u32(const void* p) {
    uint32_t a;
    asm("{ .reg .u64 t; cvta.to.shared.u64 t, %1; cvt.u32.u64 %0, t; }" : "=r"(a) : "l"(p));
    return a;
}
__device__ __forceinline__ void cp16(uint32_t dst, const void* src) {
    asm volatile("cp.async.cg.shared.global [%0], [%1], 16;" :: "r"(dst), "l"(src));
}
__device__ __forceinline__ void cp_commit() { asm volatile("cp.async.commit_group;" ::: "memory"); }
__device__ __forceinline__ void cp_wait1()  { asm volatile("cp.async.wait_group 1;" ::: "memory"); }
__device__ __forceinline__ void cp_wait0()  { asm volatile("cp.async.wait_group 0;" ::: "memory"); }

__device__ __forceinline__ void mma_bf16(float* c, uint32_t a0, uint32_t a1,
                                         uint32_t a2, uint32_t a3,
                                         uint32_t b0, uint32_t b1) {
    asm volatile(
        "mma.sync.aligned.m16n8k16.row.col.f32.bf16.bf16.f32 "
        "{%0,%1,%2,%3}, {%4,%5,%6,%7}, {%8,%9}, {%0,%1,%2,%3};"
        : "+f"(c[0]), "+f"(c[1]), "+f"(c[2]), "+f"(c[3])
        : "r"(a0), "r"(a1), "r"(a2), "r"(a3), "r"(b0), "r"(b1));
}

// Sense-reversing grid barrier. All CTAs co-resident (128 on 148 SMs). State
// returns to {0,0} after an even number of uses per launch (512 per launch).
__device__ __forceinline__ void grid_barrier(unsigned* lsense, int nb) {
    __syncthreads();
    if (threadIdx.x == 0) {
        unsigned s = *lsense ^ 1u;
        __threadfence();
        if (atomicAdd(&g_bar_count, 1u) == (unsigned)(nb - 1)) {
            g_bar_count = 0u;
            __threadfence();
            atomicExch(&g_bar_sense, s);
        } else {
            volatile unsigned* vs = &g_bar_sense;
            while (*vs != s) { __nanosleep(32); }
        }
        __threadfence();
    }
    __syncthreads();
    *lsense ^= 1u;
}

// =================== conversion kernels (fp32 -> bf16 hi/lo) ==================
__global__ __launch_bounds__(256) void k_conv_pair(
    const float* __restrict__ src, __nv_bfloat16* __restrict__ dh,
    __nv_bfloat16* __restrict__ dl, int N, int Ks, int Kp)
{
    size_t total = (size_t)N * Kp;
    for (size_t idx = (size_t)blockIdx.x * blockDim.x + threadIdx.x; idx < total;
         idx += (size_t)gridDim.x * blockDim.x) {
        int n = (int)(idx / Kp), k = (int)(idx - (size_t)n * Kp);
        float v = (k < Ks) ? src[(size_t)n * Ks + k] : 0.f;
        __nv_bfloat16 hi = __float2bfloat16(v);
        dh[idx] = hi;
        dl[idx] = __float2bfloat16(v - __bfloat162float(hi));
    }
}

// ============== HMMA split-bf16 GEMM (input projections) ======================
// C[m][n] = sum_k (Ah+Al)[row(m)][k]*(Bh+Bl)[n][k] + bias[n]  (drops Al*Bl).
// CTA 256 thr, tile 128x128, K stage 32, cp.async double buffer.
#define STRD32 20                       // row stride in b32 units
#define TILE_BYTES (128 * 80)           // 10240
#define STAGE_BYTES (4 * TILE_BYTES)    // Ah, Al, Bh, Bl
#define GEMM_SMEM (2 * STAGE_BYTES)     // 81920

__global__ __launch_bounds__(256) void k_mma_gemm(
    const __nv_bfloat16* __restrict__ Ah, const __nv_bfloat16* __restrict__ Al,
    const int* __restrict__ rowidx,     // null => identity (row = m)
    int Kpad, int S,
    const __nv_bfloat16* __restrict__ Bh, const __nv_bfloat16* __restrict__ Bl,
    const float* __restrict__ bias)
{
    extern __shared__ __align__(128) char smem[];
    __shared__ int   rows_s[128];
    __shared__ float bias_s[128];

    const int tid = threadIdx.x;
    const int bn = blockIdx.x, bm = blockIdx.y;
    const uint32_t sb = smem_u32(smem);

    if (tid < 128) {
        int m = bm * 128 + tid;
        rows_s[tid] = rowidx ? rowidx[m] : m;
        bias_s[tid] = bias[bn * 128 + tid];
    }
    __syncthreads();

    auto load_stage = [&](int s) {
        uint32_t buf = sb + (uint32_t)(s & 1) * STAGE_BYTES;
        int k0 = s * 32;
#pragma unroll
        for (int i = 0; i < 8; i++) {
            int idx = tid + i * 256;          // 2048 cp16 total
            int tile = idx >> 9;
            int loc = idx & 511;
            int r = loc >> 2, c = loc & 3;
            const __nv_bfloat16* src;
            if (tile < 2) {
                src = (tile == 0 ? Ah : Al) + (size_t)rows_s[r] * Kpad + k0 + c * 8;
            } else {
                src = (tile == 2 ? Bh : Bl) + (size_t)(bn * 128 + r) * Kpad + k0 + c * 8;
            }
            cp16(buf + tile * TILE_BYTES + r * 80 + c * 16, src);
        }
        cp_commit();
    };

    load_stage(0);
    if (S > 1) load_stage(1);

    const int wid = tid >> 5, lane = tid & 31;
    const int wm = wid & 3, wn = wid >> 2;
    const int g = lane >> 2, q = lane & 3;

    float acc[2][8][4];
#pragma unroll
    for (int mt = 0; mt < 2; mt++)
#pragma unroll
        for (int nt = 0; nt < 8; nt++)
#pragma unroll
            for (int e = 0; e < 4; e++) acc[mt][nt][e] = 0.f;

    for (int s = 0; s < S; s++) {
        if (s + 1 < S) cp_wait1(); else cp_wait0();
        __syncthreads();
        const char* buf = smem + (size_t)(s & 1) * STAGE_BYTES;
        const uint32_t* Ah32 = (const uint32_t*)(buf);
        const uint32_t* Al32 = (const uint32_t*)(buf + TILE_BYTES);
        const uint32_t* Bh32 = (const uint32_t*)(buf + 2 * TILE_BYTES);
        const uint32_t* Bl32 = (const uint32_t*)(buf + 3 * TILE_BYTES);

#pragma unroll
        for (int kh = 0; kh < 2; kh++) {
            const int kb = kh * 8;
            uint32_t ah[2][4], al[2][4];
#pragma unroll
            for (int mt = 0; mt < 2; mt++) {
                int r0 = (wm * 32 + mt * 16 + g) * STRD32;
                int r1 = r0 + 8 * STRD32;
                ah[mt][0] = Ah32[r0 + kb + q];
                ah[mt][1] = Ah32[r1 + kb + q];
                ah[mt][2] = Ah32[r0 + kb + q + 4];
                ah[mt][3] = Ah32[r1 + kb + q + 4];
                al[mt][0] = Al32[r0 + kb + q];
                al[mt][1] = Al32[r1 + kb + q];
                al[mt][2] = Al32[r0 + kb + q + 4];
                al[mt][3] = Al32[r1 + kb + q + 4];
            }
#pragma unroll
            for (int nt = 0; nt < 8; nt++) {
                int nr = (wn * 64 + nt * 8 + g) * STRD32;
                uint32_t bh0 = Bh32[nr + kb + q];
                uint32_t bh1 = Bh32[nr + kb + q + 4];
                uint32_t bl0 = Bl32[nr + kb + q];
                uint32_t bl1 = Bl32[nr + kb + q + 4];
#pragma unroll
                for (int mt = 0; mt < 2; mt++) {
                    mma_bf16(acc[mt][nt], ah[mt][0], ah[mt][1], ah[mt][2], ah[mt][3], bh0, bh1);
                    mma_bf16(acc[mt][nt], ah[mt][0], ah[mt][1], ah[mt][2], ah[mt][3], bl0, bl1);
                    mma_bf16(acc[mt][nt], al[mt][0], al[mt][1], al[mt][2], al[mt][3], bh0, bh1);
                }
            }
        }
        __syncthreads();
        if (s + 2 < S) load_stage(s + 2);
    }

#pragma unroll
    for (int mt = 0; mt < 2; mt++) {
        int r0 = wm * 32 + mt * 16 + g;
        int m0 = bm * 128 + r0;
        int m1 = m0 + 8;
        float* p0 = g_xp + ((size_t)(m0 >> 6) * TH3) * BB + (m0 & 63);
        float* p1 = g_xp + ((size_t)(m1 >> 6) * TH3) * BB + (m1 & 63);
#pragma unroll
        for (int nt = 0; nt < 8; nt++) {
            int c = wn * 64 + nt * 8 + q * 2;
            int n0 = bn * 128 + c;
            float bv0 = bias_s[c], bv1 = bias_s[c + 1];
            p0[(size_t)n0 * BB]       = acc[mt][nt][0] + bv0;
            p0[(size_t)(n0 + 1) * BB] = acc[mt][nt][1] + bv1;
            p1[(size_t)n0 * BB]       = acc[mt][nt][2] + bv0;
            p1[(size_t)(n0 + 1) * BB] = acc[mt][nt][3] + bv1;
        }
    }
}

// ==================== persistent GRU recurrence (one layer) ===================
// Grid 128 CTAs x 512 thr. CTA owns 4 hidden cols j (12 Whh rows in SMEM).
// Warp w: jl=w&3 (which j), ksec=w>>2 (K/4 slice). Lane covers b={2l,2l+1}.
// h(t-1) staged into SMEM via cp.async by each 4-warp ksec-group (its own
// 32KB quarter, [k][b] layout identical to ys rows), then consumed via LDS.
__device__ __forceinline__ float fsigm(float x) {
    return __fdividef(1.f, 1.f + __expf(-x));
}
__device__ __forceinline__ float ftanh(float x) {
    return 1.f - __fdividef(2.f, 1.f + __expf(2.f * x));
}

#define RC_HBUF_F (HH * BB)          // 32768 floats = 128KB
#define RC_WS_F   (12 * 512)         // 6144  floats = 24KB
#define RC_RED_F  (4 * 4 * 3 * 64)   // 3072  floats = 12KB
#define RC_SMEM   ((RC_HBUF_F + RC_WS_F + RC_RED_F + 16) * 4)

__global__ __launch_bounds__(512, 1) void k_recur(
    const float* __restrict__ Whh,   // [3H][H]
    const float* __restrict__ bhh,   // [3H]
    int layer)
{
    extern __shared__ __align__(16) float dyn[];
    float* hbuf  = dyn;                          // [512][64]
    float* Ws    = dyn + RC_HBUF_F;              // [12][512]
    float* red   = Ws + RC_WS_F;                 // [4 ksec][4 jl][3 gate][64 b]
    float* bhh_s = red + RC_RED_F;               // [12]

    float* __restrict__ ys = layer ? g_ys1 : g_ys0;
    const float* __restrict__ xp = g_xp;

    const int tid   = threadIdx.x;
    const int jbase = blockIdx.x * 4;
    const int nb    = gridDim.x;

    for (int idx = tid; idx < 12 * 512; idx += 512) {
        int lr = idx >> 9, k = idx & 511;
        int g = lr >> 2, jl = lr & 3;
        Ws[idx] = Whh[((size_t)(g * HH + jbase + jl)) * HH + k];
    }
    if (tid < 12) {
        int g = tid >> 2, jl = tid & 3;
        bhh_s[tid] = bhh[g * HH + jbase + jl];
    }
    __syncthreads();

    const int warp = tid >> 5;
    const int lane = tid & 31;
    const int jl   = warp & 3;
    const int ksec = warp >> 2;
    const int gtid = tid & 127;                 // index within 4-warp ksec-group

    const float* w0 = Ws + (0 * 4 + jl) * 512 + ksec * 128;
    const float* w1 = Ws + (1 * 4 + jl) * 512 + ksec * 128;
    const float* w2 = Ws + (2 * 4 + jl) * 512 + ksec * 128;

    const uint32_t hq_s = smem_u32(hbuf) + (uint32_t)(ksec * 8192) * 4u;
    const float* hq4 = hbuf + ksec * 8192 + 2 * lane;

    // tail-thread persistent state (tid < 256)
    const int rjl = tid >> 6, rb = tid & 63;
    float hq = 0.f;

    unsigned lsense = 0;

    for (int t = 0; t < TT; t++) {
        // ---- xp prefetch (consumed in tail, after the matvec) ----
        float xr = 0.f, xz = 0.f, xn = 0.f;
        if (tid < 256) {
            const float* xpb = xp + (size_t)t * TH3 * BB + rb;
            int j = jbase + rjl;
            xr = __ldcg(xpb + (size_t)(0 * HH + j) * BB);
            xz = __ldcg(xpb + (size_t)(1 * HH + j) * BB);
            xn = __ldcg(xpb + (size_t)(2 * HH + j) * BB);
        }

        if (t > 0) {
            // ---- stage this group's h quarter: global [k][b] -> SMEM ----
            const float* src = ys + ((size_t)(t - 1) * HH + ksec * 128) * BB;
#pragma unroll
            for (int i = 0; i < 16; i++) {
                int idx = gtid + i * 128;        // 2048 x 16B = 32KB
                cp16(hq_s + (uint32_t)idx * 16u, src + idx * 4);
            }
            cp_commit();
            cp_wait0();
            asm volatile("bar.sync %0, 128;" :: "r"(ksec + 1) : "memory");

            // ---- matvec over this warp's 128-k slice (all operands SMEM) ----
            float a00 = 0.f, a01 = 0.f, a10 = 0.f, a11 = 0.f, a20 = 0.f, a21 = 0.f;
#pragma unroll 4
            for (int k4 = 0; k4 < 32; k4++) {
                const float* hk = hq4 + k4 * 256;
                float2 h0 = *(const float2*)(hk);
                float2 h1 = *(const float2*)(hk + 64);
                float2 h2 = *(const float2*)(hk + 128);
                float2 h3 = *(const float2*)(hk + 192);
                float4 wa = *(const float4*)(w0 + k4 * 4);
                float4 wb = *(const float4*)(w1 + k4 * 4);
                float4 wc = *(const float4*)(w2 + k4 * 4);
                a00 = fmaf(wa.x, h0.x, fmaf(wa.y, h1.x, fmaf(wa.z, h2.x, fmaf(wa.w, h3.x, a00))));
                a01 = fmaf(wa.x, h0.y, fmaf(wa.y, h1.y, fmaf(wa.z, h2.y, fmaf(wa.w, h3.y, a01))));
                a10 = fmaf(wb.x, h0.x, fmaf(wb.y, h1.x, fmaf(wb.z, h2.x, fmaf(wb.w, h3.x, a10))));
                a11 = fmaf(wb.x, h0.y, fmaf(wb.y, h1.y, fmaf(wb.z, h2.y, fmaf(wb.w, h3.y, a11))));
                a20 = fmaf(wc.x, h0.x, fmaf(wc.y, h1.x, fmaf(wc.z, h2.x, fmaf(wc.w, h3.x, a20))));
                a21 = fmaf(wc.x, h0.y, fmaf(wc.y, h1.y, fmaf(wc.z, h2.y, fmaf(wc.w, h3.y, a21))));
            }
            int rbi = ((ksec * 4 + jl) * 3 + 0) * 64 + 2 * lane;
            red[rbi]       = a00; red[rbi + 1]   = a01;
            red[rbi + 64]  = a10; red[rbi + 65]  = a11;
            red[rbi + 128] = a20; red[rbi + 129] = a21;
        }
        __syncthreads();

        // ---- tail: reduce 4 ksec partials, gates, h update ----
        if (tid < 256) {
            float s0 = bhh_s[0 + rjl];
            float s1 = bhh_s[4 + rjl];
            float s2 = bhh_s[8 + rjl];
            if (t > 0) {
#pragma unroll
                for (int ks = 0; ks < 4; ks++) {
                    int base = ((ks * 4 + rjl) * 3) * 64 + rb;
                    s0 += red[base];
                    s1 += red[base + 64];
                    s2 += red[base + 128];
                }
            }
            float r = fsigm(xr + s0);
            float z = fsigm(xz + s1);
            float n = ftanh(xn + r * s2);
            float hnew = (1.f - z) * n + z * hq;
            hq = hnew;

            int j = jbase + rjl;
            ys[((size_t)t * HH + j) * BB + rb] = hnew;

            // layer 0: fuse the transpose + bf16 hi/lo convert for layer-1 GEMM
            if (layer == 0) {
                __nv_bfloat16 hi = __float2bfloat16(hnew);
                __nv_bfloat16 lo = __float2bfloat16(hnew - __bfloat162float(hi));
                size_t o = ((size_t)t * 64 + rb) * KP1 + j;
                g_a1h[o] = hi;
                g_a1l[o] = lo;
            }
        }
        grid_barrier(&lsense, nb);
    }
}

// ==================== mean over batch + FC head ===============================
__global__ __launch_bounds__(256) void k_pool(
    const float* __restrict__ fcW,
    const float* __restrict__ fcb,
    float*       __restrict__ out)
{
    int t = blockIdx.x;
    const float* base = g_ys1 + (size_t)t * HH * BB;
    int w = threadIdx.x >> 5, l = threadIdx.x & 31;

    float acc[LL];
#pragma unroll
    for (int j = 0; j < LL; j++) acc[j] = 0.f;

    for (int h = w; h < HH; h += 8) {
        float s = base[h * BB + l] + base[h * BB + 32 + l];
#pragma unroll
        for (int off = 16; off >= 1; off >>= 1)
            s += __shfl_xor_sync(0xffffffffu, s, off);
        if (l == 0) {
            float p = s * (1.f / 64.f);
#pragma unroll
            for (int j = 0; j < LL; j++) acc[j] = fmaf(p, fcW[j * HH + h], acc[j]);
        }
    }
    __shared__ float sred[8][LL];
    if (l == 0) {
#pragma unroll
        for (int j = 0; j < LL; j++) sred[w][j] = acc[j];
    }
    __syncthreads();
    if (threadIdx.x < LL) {
        float s = fcb[threadIdx.x];
#pragma unroll
        for (int ww = 0; ww < 8; ww++) s += sred[ww][threadIdx.x];
        out[t * LL + threadIdx.x] = s;
    }
}

// ============================== launch ========================================
extern "C" void kernel_launch(void* const* d_in, const int* in_sizes, int n_in,
                              void* d_out, int out_size) {
    const int*   texts = (const int*)  d_in[0];
    const float* emb   = (const float*)d_in[1];
    const float* Wih0  = (const float*)d_in[2];
    const float* Whh0  = (const float*)d_in[3];
    const float* bih0  = (const float*)d_in[4];
    const float* bhh0  = (const float*)d_in[5];
    const float* Wih1  = (const float*)d_in[6];
    const float* Whh1  = (const float*)d_in[7];
    const float* bih1  = (const float*)d_in[8];
    const float* bhh1  = (const float*)d_in[9];
    const float* fcW   = (const float*)d_in[10];
    const float* fcb   = (const float*)d_in[11];
    float* out = (float*)d_out;

    cudaFuncSetAttribute(k_mma_gemm, cudaFuncAttributeMaxDynamicSharedMemorySize,
                         GEMM_SMEM);
    cudaFuncSetAttribute(k_recur, cudaFuncAttributeMaxDynamicSharedMemorySize,
                         RC_SMEM);

    // resolve device-global scratch addresses for kernel params
    __nv_bfloat16 *embh, *embl, *w0h, *w0l, *w1h, *w1l, *a1h, *a1l;
    cudaGetSymbolAddress((void**)&embh, g_embh);
    cudaGetSymbolAddress((void**)&embl, g_embl);
    cudaGetSymbolAddress((void**)&w0h,  g_w0h);
    cudaGetSymbolAddress((void**)&w0l,  g_w0l);
    cudaGetSymbolAddress((void**)&w1h,  g_w1h);
    cudaGetSymbolAddress((void**)&w1l,  g_w1l);
    cudaGetSymbolAddress((void**)&a1h,  g_a1h);
    cudaGetSymbolAddress((void**)&a1l,  g_a1l);

    dim3 gemm_grid(TH3 / 128, (TT * BB) / 128);   // (12, 256)

    // conversions (static operands)
    k_conv_pair<<<8192, 256>>>(emb,  embh, embl, 30000, EE, KP0);
    k_conv_pair<<<1024, 256>>>(Wih0, w0h,  w0l,  TH3,   EE, KP0);
    k_conv_pair<<<1024, 256>>>(Wih1, w1h,  w1l,  TH3,   HH, KP1);

    // Layer 0: xp = emb[texts] @ Wih0^T + bih0 (HMMA), then recurrence
    // (recurrence also emits a1h/a1l for the layer-1 GEMM)
    k_mma_gemm<<<gemm_grid, 256, GEMM_SMEM>>>(embh, embl, texts, KP0, KP0 / 32,
                                              w0h, w0l, bih0);
    k_recur<<<128, 512, RC_SMEM>>>(Whh0, bhh0, 0);

    // Layer 1: xp = ys0 @ Wih1^T + bih1 (HMMA), then recurrence
    k_mma_gemm<<<gemm_grid, 256, GEMM_SMEM>>>(a1h, a1l, nullptr, KP1, KP1 / 32,
                                              w1h, w1l, bih1);
    k_recur<<<128, 512, RC_SMEM>>>(Whh1, bhh1, 1);

    // Head
    k_pool<<<TT, 256>>>(fcW, fcb, out);
}

// round 15
// speedup vs baseline: 1.7634x; 1.2610x over previous
#include <cuda_runtime.h>
#include <cuda_bf16.h>
#include <math.h>
#include <cstdint>

// Problem dims
#define TT   512
#define BB   64
#define EE   300
#define HH   512
#define LL   5
#define TH3  1536   // 3*H

#define KP0  320    // padded K for layer-0 input GEMM (E=300 -> 320)
#define KP1  512    // K for layer-1 input GEMM

// ---------------- scratch (device globals; no allocation allowed) -------------
__device__ float g_xp [(size_t)TT * TH3 * BB];   // input projections [T][3H][B]
__device__ float g_ys1[(size_t)TT * HH  * BB];   // layer1 hidden seq [T][H][B]

// split-bf16 (hi+lo) operands for tensor-core GEMMs
__device__ __nv_bfloat16 g_embh[(size_t)30000 * KP0];
__device__ __nv_bfloat16 g_embl[(size_t)30000 * KP0];
__device__ __nv_bfloat16 g_w0h [(size_t)TH3 * KP0];
__device__ __nv_bfloat16 g_w0l [(size_t)TH3 * KP0];
__device__ __nv_bfloat16 g_w1h [(size_t)TH3 * KP1];
__device__ __nv_bfloat16 g_w1l [(size_t)TH3 * KP1];
__device__ __nv_bfloat16 g_a1h [(size_t)TT * BB * KP1];   // ys0 transposed [m][k]
__device__ __nv_bfloat16 g_a1l [(size_t)TT * BB * KP1];

// Whh split-bf16 for the tensor-core recurrence
__device__ __nv_bfloat16 g_whh0h[(size_t)TH3 * HH];
__device__ __nv_bfloat16 g_whh0l[(size_t)TH3 * HH];
__device__ __nv_bfloat16 g_whh1h[(size_t)TH3 * HH];
__device__ __nv_bfloat16 g_whh1l[(size_t)TH3 * HH];

// h broadcast in B-fragment-packed form: [buf 2][c 32][q 4][b 64] u128
// u128 = {bh0, bh1, bl0, bl1}; bh0 = pack(hi[16c+2q][b], hi[16c+2q+1][b]),
// bh1 = same k+8; bl* = lo parts.
__device__ uint4 g_hU[(size_t)2 * 32 * 4 * 64];

// grid barrier state (self-resetting; zero at launch start/end)
__device__ unsigned g_bar_count = 0;
__device__ unsigned g_bar_sense = 0;

// ======================= helpers (base ISA only; no sm_103a-only ops) =========
__device__ __forceinline__ uint32_t smem_u32(const void* p) {
    uint32_t a;
    asm("{ .reg .u64 t; cvta.to.shared.u64 t, %1; cvt.u32.u64 %0, t; }" : "=r"(a) : "l"(p));
    return a;
}
__device__ __forceinline__ void cp16(uint32_t dst, const void* src) {
    asm volatile("cp.async.cg.shared.global [%0], [%1], 16;" :: "r"(dst), "l"(src));
}
__device__ __forceinline__ void cp_commit() { asm volatile("cp.async.commit_group;" ::: "memory"); }
__device__ __forceinline__ void cp_wait1()  { asm volatile("cp.async.wait_group 1;" ::: "memory"); }
__device__ __forceinline__ void cp_wait0()  { asm volatile("cp.async.wait_group 0;" ::: "memory"); }

__device__ __forceinline__ void mma_bf16(float* c, uint32_t a0, uint32_t a1,
                                         uint32_t a2, uint32_t a3,
                                         uint32_t b0, uint32_t b1) {
    asm volatile(
        "mma.sync.aligned.m16n8k16.row.col.f32.bf16.bf16.f32 "
        "{%0,%1,%2,%3}, {%4,%5,%6,%7}, {%8,%9}, {%0,%1,%2,%3};"
        : "+f"(c[0]), "+f"(c[1]), "+f"(c[2]), "+f"(c[3])
        : "r"(a0), "r"(a1), "r"(a2), "r"(a3), "r"(b0), "r"(b1));
}

// Sense-reversing grid barrier. All CTAs co-resident (128 on 148 SMs). State
// returns to {0,0} after an even number of uses per launch (512 per launch).
__device__ __forceinline__ void grid_barrier(unsigned* lsense, int nb) {
    __syncthreads();
    if (threadIdx.x == 0) {
        unsigned s = *lsense ^ 1u;
        __threadfence();
        if (atomicAdd(&g_bar_count, 1u) == (unsigned)(nb - 1)) {
            g_bar_count = 0u;
            __threadfence();
            atomicExch(&g_bar_sense, s);
        } else {
            volatile unsigned* vs = &g_bar_sense;
            while (*vs != s) { __nanosleep(32); }
        }
        __threadfence();
    }
    __syncthreads();
    *lsense ^= 1u;
}

// =================== conversion kernels (fp32 -> bf16 hi/lo) ==================
__global__ __launch_bounds__(256) void k_conv_pair(
    const float* __restrict__ src, __nv_bfloat16* __restrict__ dh,
    __nv_bfloat16* __restrict__ dl, int N, int Ks, int Kp)
{
    size_t total = (size_t)N * Kp;
    for (size_t idx = (size_t)blockIdx.x * blockDim.x + threadIdx.x; idx < total;
         idx += (size_t)gridDim.x * blockDim.x) {
        int n = (int)(idx / Kp), k = (int)(idx - (size_t)n * Kp);
        float v = (k < Ks) ? src[(size_t)n * Ks + k] : 0.f;
        __nv_bfloat16 hi = __float2bfloat16(v);
        dh[idx] = hi;
        dl[idx] = __float2bfloat16(v - __bfloat162float(hi));
    }
}

// ============== HMMA split-bf16 GEMM (input projections) ======================
// C[m][n] = sum_k (Ah+Al)[row(m)][k]*(Bh+Bl)[n][k] + bias[n]  (drops Al*Bl).
// CTA 256 thr, tile 128x128, K stage 32, cp.async double buffer.
#define STRD32 20                       // row stride in b32 units
#define TILE_BYTES (128 * 80)           // 10240
#define STAGE_BYTES (4 * TILE_BYTES)    // Ah, Al, Bh, Bl
#define GEMM_SMEM (2 * STAGE_BYTES)     // 81920

__global__ __launch_bounds__(256) void k_mma_gemm(
    const __nv_bfloat16* __restrict__ Ah, const __nv_bfloat16* __restrict__ Al,
    const int* __restrict__ rowidx,     // null => identity (row = m)
    int Kpad, int S,
    const __nv_bfloat16* __restrict__ Bh, const __nv_bfloat16* __restrict__ Bl,
    const float* __restrict__ bias)
{
    extern __shared__ __align__(128) char smem[];
    __shared__ int   rows_s[128];
    __shared__ float bias_s[128];

    const int tid = threadIdx.x;
    const int bn = blockIdx.x, bm = blockIdx.y;
    const uint32_t sb = smem_u32(smem);

    if (tid < 128) {
        int m = bm * 128 + tid;
        rows_s[tid] = rowidx ? rowidx[m] : m;
        bias_s[tid] = bias[bn * 128 + tid];
    }
    __syncthreads();

    auto load_stage = [&](int s) {
        uint32_t buf = sb + (uint32_t)(s & 1) * STAGE_BYTES;
        int k0 = s * 32;
#pragma unroll
        for (int i = 0; i < 8; i++) {
            int idx = tid + i * 256;          // 2048 cp16 total
            int tile = idx >> 9;
            int loc = idx & 511;
            int r = loc >> 2, c = loc & 3;
            const __nv_bfloat16* src;
            if (tile < 2) {
                src = (tile == 0 ? Ah : Al) + (size_t)rows_s[r] * Kpad + k0 + c * 8;
            } else {
                src = (tile == 2 ? Bh : Bl) + (size_t)(bn * 128 + r) * Kpad + k0 + c * 8;
            }
            cp16(buf + tile * TILE_BYTES + r * 80 + c * 16, src);
        }
        cp_commit();
    };

    load_stage(0);
    if (S > 1) load_stage(1);

    const int wid = tid >> 5, lane = tid & 31;
    const int wm = wid & 3, wn = wid >> 2;
    const int g = lane >> 2, q = lane & 3;

    float acc[2][8][4];
#pragma unroll
    for (int mt = 0; mt < 2; mt++)
#pragma unroll
        for (int nt = 0; nt < 8; nt++)
#pragma unroll
            for (int e = 0; e < 4; e++) acc[mt][nt][e] = 0.f;

    for (int s = 0; s < S; s++) {
        if (s + 1 < S) cp_wait1(); else cp_wait0();
        __syncthreads();
        const char* buf = smem + (size_t)(s & 1) * STAGE_BYTES;
        const uint32_t* Ah32 = (const uint32_t*)(buf);
        const uint32_t* Al32 = (const uint32_t*)(buf + TILE_BYTES);
        const uint32_t* Bh32 = (const uint32_t*)(buf + 2 * TILE_BYTES);
        const uint32_t* Bl32 = (const uint32_t*)(buf + 3 * TILE_BYTES);

#pragma unroll
        for (int kh = 0; kh < 2; kh++) {
            const int kb = kh * 8;
            uint32_t ah[2][4], al[2][4];
#pragma unroll
            for (int mt = 0; mt < 2; mt++) {
                int r0 = (wm * 32 + mt * 16 + g) * STRD32;
                int r1 = r0 + 8 * STRD32;
                ah[mt][0] = Ah32[r0 + kb + q];
                ah[mt][1] = Ah32[r1 + kb + q];
                ah[mt][2] = Ah32[r0 + kb + q + 4];
                ah[mt][3] = Ah32[r1 + kb + q + 4];
                al[mt][0] = Al32[r0 + kb + q];
                al[mt][1] = Al32[r1 + kb + q];
                al[mt][2] = Al32[r0 + kb + q + 4];
                al[mt][3] = Al32[r1 + kb + q + 4];
            }
#pragma unroll
            for (int nt = 0; nt < 8; nt++) {
                int nr = (wn * 64 + nt * 8 + g) * STRD32;
                uint32_t bh0 = Bh32[nr + kb + q];
                uint32_t bh1 = Bh32[nr + kb + q + 4];
                uint32_t bl0 = Bl32[nr + kb + q];
                uint32_t bl1 = Bl32[nr + kb + q + 4];
#pragma unroll
                for (int mt = 0; mt < 2; mt++) {
                    mma_bf16(acc[mt][nt], ah[mt][0], ah[mt][1], ah[mt][2], ah[mt][3], bh0, bh1);
                    mma_bf16(acc[mt][nt], ah[mt][0], ah[mt][1], ah[mt][2], ah[mt][3], bl0, bl1);
                    mma_bf16(acc[mt][nt], al[mt][0], al[mt][1], al[mt][2], al[mt][3], bh0, bh1);
                }
            }
        }
        __syncthreads();
        if (s + 2 < S) load_stage(s + 2);
    }

#pragma unroll
    for (int mt = 0; mt < 2; mt++) {
        int r0 = wm * 32 + mt * 16 + g;
        int m0 = bm * 128 + r0;
        int m1 = m0 + 8;
        float* p0 = g_xp + ((size_t)(m0 >> 6) * TH3) * BB + (m0 & 63);
        float* p1 = g_xp + ((size_t)(m1 >> 6) * TH3) * BB + (m1 & 63);
#pragma unroll
        for (int nt = 0; nt < 8; nt++) {
            int c = wn * 64 + nt * 8 + q * 2;
            int n0 = bn * 128 + c;
            float bv0 = bias_s[c], bv1 = bias_s[c + 1];
            p0[(size_t)n0 * BB]       = acc[mt][nt][0] + bv0;
            p0[(size_t)(n0 + 1) * BB] = acc[mt][nt][1] + bv1;
            p1[(size_t)n0 * BB]       = acc[mt][nt][2] + bv0;
            p1[(size_t)(n0 + 1) * BB] = acc[mt][nt][3] + bv1;
        }
    }
}

// ========== persistent GRU recurrence, HMMA + SMEM staging (one layer) ========
// Grid 128 CTAs x 512 thr. CTA owns 4 hidden cols j -> 12 gate rows (m16 pad).
// gh[m16][b64] = W[16][512] @ h^T via mma m16n8k16 split-bf16 (3 mma/chunk).
// Warp w: nt=w&7 (8-batch n-tile), kh=w>>3 (k-half, 16 chunks of k16).
// h(t-1) arrives pre-packed in g_hU fragment words; each warp cp.asyncs its
// own disjoint 8KB into swizzled SMEM (no intra-step bar.sync needed).
__device__ __forceinline__ float fsigm(float x) {
    return __fdividef(1.f, 1.f + __expf(-x));
}
__device__ __forceinline__ float ftanh(float x) {
    return 1.f - __fdividef(2.f, 1.f + __expf(2.f * x));
}

// SMEM: hU_s [8192 u128] 128KB + AF hi/lo [1024 u128 each] 32KB
#define RC_HU_WORDS 8192
#define RC_AF_WORDS 1024
#define RC_SMEM ((RC_HU_WORDS + 2 * RC_AF_WORDS) * 16)

// swizzled smem word index for B word (c, q, b): phase-conflict-free LDS.128
__device__ __forceinline__ int sidx(int c, int q, int b) {
    return (c * 4 + q) * 64 + ((b + 2 * q) & 63);
}

__global__ __launch_bounds__(512, 1) void k_recur(
    const __nv_bfloat16* __restrict__ Wh,   // [3H][512] bf16 hi
    const __nv_bfloat16* __restrict__ Wl,   // [3H][512] bf16 lo
    const float* __restrict__ bhh,          // [3H]
    int layer)
{
    extern __shared__ __align__(16) uint4 dynu[];
    uint4* hU_s  = dynu;                       // [32c][4q][64b] swizzled
    uint4* AF_h  = dynu + RC_HU_WORDS;         // [32c][32lane]
    uint4* AF_l  = AF_h + RC_AF_WORDS;
    __shared__ float red[2][16][64];           // [kh][m][b]
    __shared__ float bhh_s[12];

    const float* __restrict__ xp = g_xp;

    const int tid   = threadIdx.x;
    const int jbase = blockIdx.x * 4;
    const int nb    = gridDim.x;

    // ---- prepack A (W) fragments into SMEM, once ----
    const uint32_t* wh32 = (const uint32_t*)Wh;
    const uint32_t* wl32 = (const uint32_t*)Wl;
    for (int idx = tid; idx < RC_AF_WORDS; idx += 512) {
        int c = idx >> 5, lane = idx & 31;
        int g = lane >> 2, q = lane & 3;
        int kk = 16 * c + 2 * q;                // even
        // row(m) = (m>>2)*HH + jbase + (m&3), valid m<12
        int m0 = g, m1 = g + 8;
        int r0 = (m0 >> 2) * HH + jbase + (m0 & 3);
        int r1 = (m1 >> 2) * HH + jbase + (m1 & 3);
        bool v1 = (m1 < 12);
        uint4 ah, al;
        ah.x = wh32[r0 * 256 + (kk >> 1)];
        ah.y = v1 ? wh32[r1 * 256 + (kk >> 1)] : 0u;
        ah.z = wh32[r0 * 256 + ((kk + 8) >> 1)];
        ah.w = v1 ? wh32[r1 * 256 + ((kk + 8) >> 1)] : 0u;
        al.x = wl32[r0 * 256 + (kk >> 1)];
        al.y = v1 ? wl32[r1 * 256 + (kk >> 1)] : 0u;
        al.z = wl32[r0 * 256 + ((kk + 8) >> 1)];
        al.w = v1 ? wl32[r1 * 256 + ((kk + 8) >> 1)] : 0u;
        AF_h[idx] = ah;
        AF_l[idx] = al;
    }
    if (tid < 12)
        bhh_s[tid] = bhh[(tid >> 2) * HH + jbase + (tid & 3)];
    __syncthreads();

    const int warp = tid >> 5;
    const int lane = tid & 31;
    const int nt = warp & 7;
    const int kh = warp >> 3;
    const int g = lane >> 2, q = lane & 3;
    const uint32_t hU_sb = smem_u32(hU_s);

    // tail-thread persistent state (tid < 256)
    const int rjl = tid >> 6, rb = tid & 63;
    float hq = 0.f;

    unsigned lsense = 0;

    for (int t = 0; t < TT; t++) {
        // ---- stage this warp's B words for step t (h(t-1)) ----
        if (t > 0) {
            const int rbuf = (t - 1) & 1;
            const uint4* src = g_hU + (size_t)rbuf * 8192;
#pragma unroll
            for (int i = 0; i < 16; i++) {
                int w = lane + i * 32;          // 0..511
                int cc = kh * 16 + (w >> 5);
                int qq = (w >> 3) & 3;
                int bb = nt * 8 + (w & 7);
                cp16(hU_sb + (uint32_t)sidx(cc, qq, bb) * 16u,
                     src + ((size_t)cc * 4 + qq) * 64 + bb);
            }
            cp_commit();
        }

        // ---- xp prefetch (overlaps cp.async flight) ----
        float xr = 0.f, xz = 0.f, xn = 0.f;
        if (tid < 256) {
            const float* xpb = xp + (size_t)t * TH3 * BB + rb;
            int j = jbase + rjl;
            xr = __ldcg(xpb + (size_t)(0 * HH + j) * BB);
            xz = __ldcg(xpb + (size_t)(1 * HH + j) * BB);
            xn = __ldcg(xpb + (size_t)(2 * HH + j) * BB);
        }

        if (t > 0) {
            cp_wait0();   // own words only -> no bar.sync needed

            // ---- mma over this warp's 16 chunks (3 indep acc chains) ----
            float ac0[4] = {0.f, 0.f, 0.f, 0.f};
            float ac1[4] = {0.f, 0.f, 0.f, 0.f};
            float ac2[4] = {0.f, 0.f, 0.f, 0.f};
            const int bswz = sidx(0, q, nt * 8 + g);
#pragma unroll
            for (int c16 = 0; c16 < 16; c16++) {
                int c = kh * 16 + c16;
                uint4 Ah = AF_h[c * 32 + lane];
                uint4 Al = AF_l[c * 32 + lane];
                uint4 Bv = hU_s[c * 256 + bswz];
                mma_bf16(ac0, Ah.x, Ah.y, Ah.z, Ah.w, Bv.x, Bv.y);  // hi*hi
                mma_bf16(ac1, Ah.x, Ah.y, Ah.z, Ah.w, Bv.z, Bv.w);  // hi*lo
                mma_bf16(ac2, Al.x, Al.y, Al.z, Al.w, Bv.x, Bv.y);  // lo*hi
            }
            int nb0 = nt * 8 + 2 * q;
            red[kh][g][nb0]         = ac0[0] + ac1[0] + ac2[0];
            red[kh][g][nb0 + 1]     = ac0[1] + ac1[1] + ac2[1];
            red[kh][g + 8][nb0]     = ac0[2] + ac1[2] + ac2[2];
            red[kh][g + 8][nb0 + 1] = ac0[3] + ac1[3] + ac2[3];
        }
        __syncthreads();

        // ---- tail: reduce kh halves, gates, h update, fragment publish ----
        if (tid < 256) {
            float s0 = bhh_s[0 + rjl];
            float s1 = bhh_s[4 + rjl];
            float s2 = bhh_s[8 + rjl];
            if (t > 0) {
                s0 += red[0][rjl][rb]     + red[1][rjl][rb];
                s1 += red[0][4 + rjl][rb] + red[1][4 + rjl][rb];
                s2 += red[0][8 + rjl][rb] + red[1][8 + rjl][rb];
            }
            float r = fsigm(xr + s0);
            float z = fsigm(xz + s1);
            float n = ftanh(xn + r * s2);
            float hnew = (1.f - z) * n + z * hq;
            hq = hnew;

            int j = jbase + rjl;
            __nv_bfloat16 hi = __float2bfloat16(hnew);
            __nv_bfloat16 lo = __float2bfloat16(hnew - __bfloat162float(hi));

            // publish into B-fragment word: j -> (c = j>>4, r4 = j&15)
            {
                int c = j >> 4, rr = j & 15;
                int upper = (rr >= 8) ? 4 : 0;
                int rl = rr & 7;
                int qq = rl >> 1, e = rl & 1;
                size_t widx = (((size_t)(t & 1) * 32 + c) * 4 + qq) * 64 + rb;
                char* base = (char*)(g_hU + widx);
                *(__nv_bfloat16*)(base + upper + 2 * e)     = hi;
                *(__nv_bfloat16*)(base + 8 + upper + 2 * e) = lo;
            }

            if (layer == 0) {
                // fused transpose + hi/lo convert for the layer-1 GEMM
                size_t o = ((size_t)t * 64 + rb) * KP1 + j;
                g_a1h[o] = hi;
                g_a1l[o] = lo;
            } else {
                g_ys1[((size_t)t * HH + j) * BB + rb] = hnew;
            }
        }
        grid_barrier(&lsense, nb);
    }
}

// ==================== mean over batch + FC head ===============================
__global__ __launch_bounds__(256) void k_pool(
    const float* __restrict__ fcW,
    const float* __restrict__ fcb,
    float*       __restrict__ out)
{
    int t = blockIdx.x;
    const float* base = g_ys1 + (size_t)t * HH * BB;
    int w = threadIdx.x >> 5, l = threadIdx.x & 31;

    float acc[LL];
#pragma unroll
    for (int j = 0; j < LL; j++) acc[j] = 0.f;

    for (int h = w; h < HH; h += 8) {
        float s = base[h * BB + l] + base[h * BB + 32 + l];
#pragma unroll
        for (int off = 16; off >= 1; off >>= 1)
            s += __shfl_xor_sync(0xffffffffu, s, off);
        if (l == 0) {
            float p = s * (1.f / 64.f);
#pragma unroll
            for (int j = 0; j < LL; j++) acc[j] = fmaf(p, fcW[j * HH + h], acc[j]);
        }
    }
    __shared__ float sred[8][LL];
    if (l == 0) {
#pragma unroll
        for (int j = 0; j < LL; j++) sred[w][j] = acc[j];
    }
    __syncthreads();
    if (threadIdx.x < LL) {
        float s = fcb[threadIdx.x];
#pragma unroll
        for (int ww = 0; ww < 8; ww++) s += sred[ww][threadIdx.x];
        out[t * LL + threadIdx.x] = s;
    }
}

// ============================== launch ========================================
extern "C" void kernel_launch(void* const* d_in, const int* in_sizes, int n_in,
                              void* d_out, int out_size) {
    const int*   texts = (const int*)  d_in[0];
    const float* emb   = (const float*)d_in[1];
    const float* Wih0  = (const float*)d_in[2];
    const float* Whh0  = (const float*)d_in[3];
    const float* bih0  = (const float*)d_in[4];
    const float* bhh0  = (const float*)d_in[5];
    const float* Wih1  = (const float*)d_in[6];
    const float* Whh1  = (const float*)d_in[7];
    const float* bih1  = (const float*)d_in[8];
    const float* bhh1  = (const float*)d_in[9];
    const float* fcW   = (const float*)d_in[10];
    const float* fcb   = (const float*)d_in[11];
    float* out = (float*)d_out;

    cudaFuncSetAttribute(k_mma_gemm, cudaFuncAttributeMaxDynamicSharedMemorySize,
                         GEMM_SMEM);
    cudaFuncSetAttribute(k_recur, cudaFuncAttributeMaxDynamicSharedMemorySize,
                         RC_SMEM);

    // resolve device-global scratch addresses for kernel params
    __nv_bfloat16 *embh, *embl, *w0h, *w0l, *w1h, *w1l, *a1h, *a1l;
    __nv_bfloat16 *wh0h, *wh0l, *wh1h, *wh1l;
    cudaGetSymbolAddress((void**)&embh, g_embh);
    cudaGetSymbolAddress((void**)&embl, g_embl);
    cudaGetSymbolAddress((void**)&w0h,  g_w0h);
    cudaGetSymbolAddress((void**)&w0l,  g_w0l);
    cudaGetSymbolAddress((void**)&w1h,  g_w1h);
    cudaGetSymbolAddress((void**)&w1l,  g_w1l);
    cudaGetSymbolAddress((void**)&a1h,  g_a1h);
    cudaGetSymbolAddress((void**)&a1l,  g_a1l);
    cudaGetSymbolAddress((void**)&wh0h, g_whh0h);
    cudaGetSymbolAddress((void**)&wh0l, g_whh0l);
    cudaGetSymbolAddress((void**)&wh1h, g_whh1h);
    cudaGetSymbolAddress((void**)&wh1l, g_whh1l);

    dim3 gemm_grid(TH3 / 128, (TT * BB) / 128);   // (12, 256)

    // conversions (static operands)
    k_conv_pair<<<8192, 256>>>(emb,  embh, embl, 30000, EE, KP0);
    k_conv_pair<<<1024, 256>>>(Wih0, w0h,  w0l,  TH3,   EE, KP0);
    k_conv_pair<<<1024, 256>>>(Wih1, w1h,  w1l,  TH3,   HH, KP1);
    k_conv_pair<<<768,  256>>>(Whh0, wh0h, wh0l, TH3,   HH, HH);
    k_conv_pair<<<768,  256>>>(Whh1, wh1h, wh1l, TH3,   HH, HH);

    // Layer 0: xp = emb[texts] @ Wih0^T + bih0 (HMMA), then HMMA recurrence
    // (recurrence also emits a1h/a1l for the layer-1 GEMM)
    k_mma_gemm<<<gemm_grid, 256, GEMM_SMEM>>>(embh, embl, texts, KP0, KP0 / 32,
                                              w0h, w0l, bih0);
    k_recur<<<128, 512, RC_SMEM>>>(wh0h, wh0l, bhh0, 0);

    // Layer 1: xp = ys0 @ Wih1^T + bih1 (HMMA), then HMMA recurrence
    k_mma_gemm<<<gemm_grid, 256, GEMM_SMEM>>>(a1h, a1l, nullptr, KP1, KP1 / 32,
                                              w1h, w1l, bih1);
    k_recur<<<128, 512, RC_SMEM>>>(wh1h, wh1l, bhh1, 1);

    // Head
    k_pool<<<TT, 256>>>(fcW, fcb, out);
}